// round 12
// baseline (speedup 1.0000x reference)
#include <cuda_runtime.h>
#include <cuda_bf16.h>
#include <cstdint>
#include <math.h>

namespace {
constexpr int kB = 2, kT = 1024, kD = 1024, kH = 16, kHD = 64, kL = 4;
constexpr int kDFF = 4096, kVOCAB = 16384;
constexpr int kBT = kB * kT;
constexpr int kBH = kB * kH;
constexpr float kEPS = 1e-6f;
constexpr int KC = 32;     // k-chunk
constexpr int SP = 40;     // padded smem row stride (bf16 elems)
constexpr int NST = 2;     // pipeline stages
}

// ------------------------- static device scratch ---------------------------
__device__ float g_x[kBT * kD];
__device__ float g_qkv[3 * kBT * kD];
__device__ float g_s[(size_t)kBH * kT * kT];
__device__ float g_f13[2 * kBT * kDFF];
__device__ float g_inv[32];

__device__ __nv_bfloat16 c_h[2][kBT * kD];
__device__ __nv_bfloat16 c_o[2][kBT * kD];
__device__ __nv_bfloat16 c_g[2][kBT * kDFF];
__device__ __nv_bfloat16 b_q[2][kBH * kT * kHD];
__device__ __nv_bfloat16 b_k[2][kBH * kT * kHD];
__device__ __nv_bfloat16 b_vt[2][kBH * kHD * kT];
__device__ __nv_bfloat16 b_p[2][(size_t)kBH * kT * kT];
__device__ __nv_bfloat16 c_wqkv[2][kL * 3 * kD * kD];
__device__ __nv_bfloat16 c_wo[2][kL * kD * kD];
__device__ __nv_bfloat16 c_w13[2][kL * 2 * kDFF * kD];
__device__ __nv_bfloat16 c_w2[2][kL * kD * kDFF];
__device__ __nv_bfloat16 c_emb[2][kVOCAB * kD];

// ------------------------------ PTX helpers --------------------------------
__device__ __forceinline__ uint32_t smem_u32(const void* p) {
    uint32_t a;
    asm("{ .reg .u64 t; cvta.to.shared.u64 t, %1; cvt.u32.u64 %0, t; }" : "=r"(a) : "l"(p));
    return a;
}
__device__ __forceinline__ void cp16(uint32_t dst, const void* src) {
    asm volatile("cp.async.cg.shared.global [%0], [%1], 16;" :: "r"(dst), "l"(src));
}
__device__ __forceinline__ void cp_commit() { asm volatile("cp.async.commit_group;" ::: "memory"); }
__device__ __forceinline__ void cp_wait0() { asm volatile("cp.async.wait_group 0;" ::: "memory"); }

__device__ __forceinline__ void ldsm4(uint32_t& r0, uint32_t& r1, uint32_t& r2, uint32_t& r3,
                                      uint32_t addr) {
    asm volatile("ldmatrix.sync.aligned.m8n8.x4.shared.b16 {%0,%1,%2,%3},[%4];"
                 : "=r"(r0), "=r"(r1), "=r"(r2), "=r"(r3) : "r"(addr));
}
__device__ __forceinline__ void mma16816(float* c, const uint32_t* A, const uint32_t* B) {
    asm volatile(
        "mma.sync.aligned.m16n8k16.row.col.f32.bf16.bf16.f32 "
        "{%0,%1,%2,%3},{%4,%5,%6,%7},{%8,%9},{%0,%1,%2,%3};"
        : "+f"(c[0]), "+f"(c[1]), "+f"(c[2]), "+f"(c[3])
        : "r"(A[0]), "r"(A[1]), "r"(A[2]), "r"(A[3]), "r"(B[0]), "r"(B[1]));
}
__device__ __forceinline__ void split_bf16(float f, __nv_bfloat16& hi, __nv_bfloat16& lo) {
    hi = __float2bfloat16(f);
    lo = __float2bfloat16(f - __bfloat162float(hi));
}

// ------------- batched fp32 -> (hi,lo) bf16 converter (z-indexed) ----------
struct CvtP {
    const float* src[4];
    __nv_bfloat16 *hi[4], *lo[4];
    long long strideE[4];
    int n4, seg4;
};

__global__ void cvt_batch(CvtP p) {
    const int z = blockIdx.y;
    const float4* src = reinterpret_cast<const float4*>(p.src[z]);
    __nv_bfloat16* hi = p.hi[z];
    __nv_bfloat16* lo = p.lo[z];
    const long long strE = p.strideE[z];
    const int stride = gridDim.x * blockDim.x;
    for (int i = blockIdx.x * blockDim.x + threadIdx.x; i < p.n4; i += stride) {
        float4 v = src[i];
        int l = i / p.seg4, r = i - l * p.seg4;
        long long d = (long long)l * strE + (long long)r * 4;
        __nv_bfloat16 h0, h1, h2, h3, l0, l1, l2, l3;
        split_bf16(v.x, h0, l0); split_bf16(v.y, h1, l1);
        split_bf16(v.z, h2, l2); split_bf16(v.w, h3, l3);
        *reinterpret_cast<__nv_bfloat162*>(hi + d)     = __nv_bfloat162(h0, h1);
        *reinterpret_cast<__nv_bfloat162*>(hi + d + 2) = __nv_bfloat162(h2, h3);
        *reinterpret_cast<__nv_bfloat162*>(lo + d)     = __nv_bfloat162(l0, l1);
        *reinterpret_cast<__nv_bfloat162*>(lo + d + 2) = __nv_bfloat162(l2, l3);
    }
}

// ------------- generic HMMA split-bf16 GEMM: C[M,N] = A*B^T ----------------
// Batched over blockIdx.z. A,B bf16 hi/lo (NT layout: B[N,K]).
// Epilogues: 0 = fp32 store, 1 = fp32 add, 2 = fp32 store *0.125, 3 = bf16 hi/lo.
// 128-thread configs: 3 CTAs/SM, all-fragments-prefetch mainloop (reg budget 170).
// 256-thread configs: 2 CTAs/SM, staged mainloop (reg budget 128).
struct GemmP {
    const __nv_bfloat16 *Ah, *Al, *Bh, *Bl;
    float* C;
    __nv_bfloat16 *Chi, *Clo;
    long long strA, strB;               // per-z element offsets for A, B
    int czDiv; long long czOut, czIn;   // C off = (z/czDiv)*czOut + (z%czDiv)*czIn
    int K, ldC;
};

template <int BM_, int BN_, int WR, int WC, int EPI>
__global__ void __launch_bounds__(WR * WC * 32, (WR * WC * 32) <= 128 ? 3 : 2)
gemm_t(GemmP a) {
    constexpr int NT = WR * WC * 32;
    constexpr int ST_AH = 0, ST_AL = BM_ * SP;
    constexpr int ST_BH = 2 * BM_ * SP, ST_BL = 2 * BM_ * SP + BN_ * SP;
    constexpr int SE = 2 * BM_ * SP + 2 * BN_ * SP;
    extern __shared__ __nv_bfloat16 sm[];

    const int tid = threadIdx.x;
    const int w = tid >> 5, lane = tid & 31;
    const int wm = w / WC, wn = w % WC;
    const int K = a.K;
    const int bm = blockIdx.y * BM_, bn = blockIdx.x * BN_;
    const int z = blockIdx.z;

    const long long cOff = (long long)(z / a.czDiv) * a.czOut +
                           (long long)(z % a.czDiv) * a.czIn;
    const __nv_bfloat16* Ahg = a.Ah + (long long)z * a.strA + (long long)bm * K;
    const __nv_bfloat16* Alg = a.Al + (long long)z * a.strA + (long long)bm * K;
    const __nv_bfloat16* Bhg = a.Bh + (long long)z * a.strB + (long long)bn * K;
    const __nv_bfloat16* Blg = a.Bl + (long long)z * a.strB + (long long)bn * K;

    float acc[4][4][4];
#pragma unroll
    for (int i = 0; i < 4; i++)
#pragma unroll
        for (int j = 0; j < 4; j++)
#pragma unroll
            for (int q = 0; q < 4; q++) acc[i][j][q] = 0.f;

    // one chunk = KC=32 columns: 4 x 16B segments per row
    auto load_chunk = [&](int st, int kt) {
        __nv_bfloat16* s = sm + st * SE;
        const int kof = kt * KC;
#pragma unroll 2
        for (int idx = tid; idx < BM_ * 4; idx += NT) {
            int row = idx >> 2, sg = idx & 3;
            long long go = (long long)row * K + kof + sg * 8;
            cp16(smem_u32(s + ST_AH + row * SP + sg * 8), Ahg + go);
            cp16(smem_u32(s + ST_AL + row * SP + sg * 8), Alg + go);
        }
#pragma unroll 2
        for (int idx = tid; idx < BN_ * 4; idx += NT) {
            int row = idx >> 2, sg = idx & 3;
            long long go = (long long)row * K + kof + sg * 8;
            cp16(smem_u32(s + ST_BH + row * SP + sg * 8), Bhg + go);
            cp16(smem_u32(s + ST_BL + row * SP + sg * 8), Blg + go);
        }
        cp_commit();
    };

    const int a_row = wm * 64 + (lane & 15);
    const int a_kof = (lane >> 4) * 8;
    const int b_row = wn * 32 + (lane >> 4) * 8 + (lane & 7);
    const int b_kof = ((lane >> 3) & 1) * 8;

    const int nch = K / KC;
    load_chunk(0, 0);

    for (int kt = 0; kt < nch; kt++) {
        cp_wait0();            // chunk kt complete (only it is outstanding)
        __syncthreads();       // all warps done computing chunk kt-1
        if (kt + 1 < nch) load_chunk((kt + 1) & 1, kt + 1);   // overlaps compute(kt)

        const __nv_bfloat16* s = sm + (kt & 1) * SE;
#pragma unroll
        for (int k16 = 0; k16 < KC / 16; k16++) {
            const int kk = k16 * 16;
            uint32_t bh_[4][2], bl_[4][2];
#pragma unroll
            for (int nt = 0; nt < 2; nt++) {
                ldsm4(bh_[2 * nt][0], bh_[2 * nt][1], bh_[2 * nt + 1][0], bh_[2 * nt + 1][1],
                      smem_u32(s + ST_BH + (b_row + nt * 16) * SP + b_kof + kk));
                ldsm4(bl_[2 * nt][0], bl_[2 * nt][1], bl_[2 * nt + 1][0], bl_[2 * nt + 1][1],
                      smem_u32(s + ST_BL + (b_row + nt * 16) * SP + b_kof + kk));
            }
            if constexpr (NT <= 128) {
                // reg budget 170: prefetch ALL fragments, then run 48 mma stall-free
                uint32_t af[4][4], al_[4][4];
#pragma unroll
                for (int mi = 0; mi < 4; mi++)
                    ldsm4(af[mi][0], af[mi][1], af[mi][2], af[mi][3],
                          smem_u32(s + ST_AH + (a_row + mi * 16) * SP + a_kof + kk));
#pragma unroll
                for (int mi = 0; mi < 4; mi++)
                    ldsm4(al_[mi][0], al_[mi][1], al_[mi][2], al_[mi][3],
                          smem_u32(s + ST_AL + (a_row + mi * 16) * SP + a_kof + kk));
#pragma unroll
                for (int mi = 0; mi < 4; mi++)
#pragma unroll
                    for (int ni = 0; ni < 4; ni++) mma16816(acc[mi][ni], af[mi], bh_[ni]);
#pragma unroll
                for (int mi = 0; mi < 4; mi++)
#pragma unroll
                    for (int ni = 0; ni < 4; ni++) mma16816(acc[mi][ni], af[mi], bl_[ni]);
#pragma unroll
                for (int mi = 0; mi < 4; mi++)
#pragma unroll
                    for (int ni = 0; ni < 4; ni++) mma16816(acc[mi][ni], al_[mi], bh_[ni]);
            } else {
                // reg budget 128: staged (reload A for pass 3)
                uint32_t af[4][4];
#pragma unroll
                for (int mi = 0; mi < 4; mi++)
                    ldsm4(af[mi][0], af[mi][1], af[mi][2], af[mi][3],
                          smem_u32(s + ST_AH + (a_row + mi * 16) * SP + a_kof + kk));
#pragma unroll
                for (int mi = 0; mi < 4; mi++)
#pragma unroll
                    for (int ni = 0; ni < 4; ni++) mma16816(acc[mi][ni], af[mi], bh_[ni]);
#pragma unroll
                for (int mi = 0; mi < 4; mi++)
#pragma unroll
                    for (int ni = 0; ni < 4; ni++) mma16816(acc[mi][ni], af[mi], bl_[ni]);
#pragma unroll
                for (int mi = 0; mi < 4; mi++)
                    ldsm4(af[mi][0], af[mi][1], af[mi][2], af[mi][3],
                          smem_u32(s + ST_AL + (a_row + mi * 16) * SP + a_kof + kk));
#pragma unroll
                for (int mi = 0; mi < 4; mi++)
#pragma unroll
                    for (int ni = 0; ni < 4; ni++) mma16816(acc[mi][ni], af[mi], bh_[ni]);
            }
        }
    }

    // epilogue
    const int ldC = a.ldC;
#pragma unroll
    for (int mi = 0; mi < 4; mi++) {
#pragma unroll
        for (int ni = 0; ni < 4; ni++) {
            int row0 = bm + wm * 64 + mi * 16 + (lane >> 2);
            int col = bn + wn * 32 + ni * 8 + (lane & 3) * 2;
            long long o0 = cOff + (long long)row0 * ldC + col;
            long long o1 = cOff + (long long)(row0 + 8) * ldC + col;
            if (EPI == 3) {
                __nv_bfloat16 h0, h1, h2, h3, l0, l1, l2, l3;
                split_bf16(acc[mi][ni][0], h0, l0); split_bf16(acc[mi][ni][1], h1, l1);
                split_bf16(acc[mi][ni][2], h2, l2); split_bf16(acc[mi][ni][3], h3, l3);
                *reinterpret_cast<__nv_bfloat162*>(a.Chi + o0) = __nv_bfloat162(h0, h1);
                *reinterpret_cast<__nv_bfloat162*>(a.Chi + o1) = __nv_bfloat162(h2, h3);
                *reinterpret_cast<__nv_bfloat162*>(a.Clo + o0) = __nv_bfloat162(l0, l1);
                *reinterpret_cast<__nv_bfloat162*>(a.Clo + o1) = __nv_bfloat162(l2, l3);
            } else {
                float sc = (EPI == 2) ? 0.125f : 1.f;
                float2 v0 = make_float2(acc[mi][ni][0] * sc, acc[mi][ni][1] * sc);
                float2 v1 = make_float2(acc[mi][ni][2] * sc, acc[mi][ni][3] * sc);
                if (EPI == 1) {
                    float2 p0 = *reinterpret_cast<const float2*>(a.C + o0);
                    float2 p1 = *reinterpret_cast<const float2*>(a.C + o1);
                    v0.x += p0.x; v0.y += p0.y; v1.x += p1.x; v1.y += p1.y;
                }
                *reinterpret_cast<float2*>(a.C + o0) = v0;
                *reinterpret_cast<float2*>(a.C + o1) = v1;
            }
        }
    }
}

// ------------------------------- elementwise -------------------------------
__global__ void embed_kernel(const int* __restrict__ tok, const float* __restrict__ emb) {
    int row = blockIdx.x;
    const float4* src = reinterpret_cast<const float4*>(emb + (size_t)tok[row] * kD);
    float4* dst = reinterpret_cast<float4*>(g_x + (size_t)row * kD);
    for (int i = threadIdx.x; i < kD / 4; i += blockDim.x) dst[i] = src[i];
}

__global__ void rmsnorm_cvt(const float* __restrict__ in, const float* __restrict__ w,
                            __nv_bfloat16* __restrict__ oh, __nv_bfloat16* __restrict__ ol) {
    int row = blockIdx.x, tid = threadIdx.x;
    float4 v = reinterpret_cast<const float4*>(in + (size_t)row * kD)[tid];
    __shared__ float red[256];
    red[tid] = v.x * v.x + v.y * v.y + v.z * v.z + v.w * v.w;
    __syncthreads();
    for (int off = 128; off > 0; off >>= 1) {
        if (tid < off) red[tid] += red[tid + off];
        __syncthreads();
    }
    float inv = rsqrtf(red[0] * (1.f / kD) + kEPS);
    float4 wv = reinterpret_cast<const float4*>(w)[tid];
    float y[4] = {v.x * inv * wv.x, v.y * inv * wv.y, v.z * inv * wv.z, v.w * inv * wv.w};
    __nv_bfloat16 h[4], l[4];
#pragma unroll
    for (int j = 0; j < 4; j++) split_bf16(y[j], h[j], l[j]);
    size_t o = (size_t)row * kD + tid * 4;
    reinterpret_cast<__nv_bfloat162*>(oh + o)[0] = __nv_bfloat162(h[0], h[1]);
    reinterpret_cast<__nv_bfloat162*>(oh + o)[1] = __nv_bfloat162(h[2], h[3]);
    reinterpret_cast<__nv_bfloat162*>(ol + o)[0] = __nv_bfloat162(l[0], l[1]);
    reinterpret_cast<__nv_bfloat162*>(ol + o)[1] = __nv_bfloat162(l[2], l[3]);
}

__global__ void rope_init() {
    int i = threadIdx.x;
    if (i < 32) g_inv[i] = (float)(1.0 / pow(10000.0, (double)(2 * i) / (double)kHD));
}

// RoPE on q,k (from g_qkv fp32) -> hi/lo head-major [bh][t][64]
__global__ void rope_cvt(const int* __restrict__ pos) {
    int row = blockIdx.x, idx = threadIdx.x;
    int h = idx >> 5, i = idx & 31;
    int b = row >> 10, t = row & 1023;
    float ang = (float)pos[row] * g_inv[i];
    float s, c;
    sincosf(ang, &s, &c);
    const float* qs = g_qkv + (size_t)row * kD + h * kHD + 2 * i;
    const float* ks = qs + (size_t)kBT * kD;
    float qr = qs[0], qi = qs[1], kr = ks[0], ki = ks[1];
    float q0 = qr * c - qi * s, q1 = qr * s + qi * c;
    float k0 = kr * c - ki * s, k1 = kr * s + ki * c;
    size_t dst = ((size_t)(b * kH + h) * kT + t) * kHD + 2 * i;
    __nv_bfloat16 h0, h1, l0, l1;
    split_bf16(q0, h0, l0); split_bf16(q1, h1, l1);
    *reinterpret_cast<__nv_bfloat162*>(&b_q[0][dst]) = __nv_bfloat162(h0, h1);
    *reinterpret_cast<__nv_bfloat162*>(&b_q[1][dst]) = __nv_bfloat162(l0, l1);
    split_bf16(k0, h0, l0); split_bf16(k1, h1, l1);
    *reinterpret_cast<__nv_bfloat162*>(&b_k[0][dst]) = __nv_bfloat162(h0, h1);
    *reinterpret_cast<__nv_bfloat162*>(&b_k[1][dst]) = __nv_bfloat162(l0, l1);
}

// V transpose: g_qkv v [bt][d] -> b_vt hi/lo [bh][hd][t]
__global__ void v_cvt() {
    __shared__ float vs[64][65];
    int bh = blockIdx.y, b = bh >> 4, h = bh & 15;
    int t0 = blockIdx.x * 64;
    const float* src = g_qkv + 2LL * kBT * kD + ((size_t)(b * kT + t0)) * kD + h * kHD;
#pragma unroll
    for (int it = 0; it < 16; it++) {
        int e = it * 256 + threadIdx.x;
        int tr = e >> 6, hd = e & 63;
        vs[tr][hd] = src[(size_t)tr * kD + hd];
    }
    __syncthreads();
#pragma unroll
    for (int it = 0; it < 16; it++) {
        int e = it * 256 + threadIdx.x;
        int hd = e >> 6, tc = e & 63;
        __nv_bfloat16 hi, lo;
        split_bf16(vs[tc][hd], hi, lo);
        size_t dst = ((size_t)bh * kHD + hd) * kT + t0 + tc;
        b_vt[0][dst] = hi;
        b_vt[1][dst] = lo;
    }
}

// softmax over rows of g_s -> bf16 hi/lo b_p
__global__ void softmax_cvt() {
    size_t row = blockIdx.x;
    const float* p = g_s + row * (size_t)kT;
    __shared__ float red[256];
    int tid = threadIdx.x;
    float v[4], m = -1e30f;
#pragma unroll
    for (int j = 0; j < 4; j++) { v[j] = p[tid + j * 256]; m = fmaxf(m, v[j]); }
    red[tid] = m;
    __syncthreads();
    for (int off = 128; off > 0; off >>= 1) {
        if (tid < off) red[tid] = fmaxf(red[tid], red[tid + off]);
        __syncthreads();
    }
    float M = red[0];
    __syncthreads();
    float sum = 0.f;
#pragma unroll
    for (int j = 0; j < 4; j++) { v[j] = expf(v[j] - M); sum += v[j]; }
    red[tid] = sum;
    __syncthreads();
    for (int off = 128; off > 0; off >>= 1) {
        if (tid < off) red[tid] += red[tid + off];
        __syncthreads();
    }
    float inv = 1.f / red[0];
#pragma unroll
    for (int j = 0; j < 4; j++) {
        __nv_bfloat16 hi, lo;
        split_bf16(v[j] * inv, hi, lo);
        size_t o = row * kT + tid + j * 256;
        b_p[0][o] = hi;
        b_p[1][o] = lo;
    }
}

__global__ void silu_cvt() {
    int i4 = blockIdx.x * 256 + threadIdx.x;
    float4 a = reinterpret_cast<const float4*>(g_f13)[i4];
    float4 b = reinterpret_cast<const float4*>(g_f13)[i4 + kBT * kDFF / 4];
    float y[4] = {a.x / (1.f + expf(-a.x)) * b.x, a.y / (1.f + expf(-a.y)) * b.y,
                  a.z / (1.f + expf(-a.z)) * b.z, a.w / (1.f + expf(-a.w)) * b.w};
    __nv_bfloat16 h[4], l[4];
#pragma unroll
    for (int j = 0; j < 4; j++) split_bf16(y[j], h[j], l[j]);
    size_t o = (size_t)i4 * 4;
    reinterpret_cast<__nv_bfloat162*>(c_g[0] + o)[0] = __nv_bfloat162(h[0], h[1]);
    reinterpret_cast<__nv_bfloat162*>(c_g[0] + o)[1] = __nv_bfloat162(h[2], h[3]);
    reinterpret_cast<__nv_bfloat162*>(c_g[1] + o)[0] = __nv_bfloat162(l[0], l[1]);
    reinterpret_cast<__nv_bfloat162*>(c_g[1] + o)[1] = __nv_bfloat162(l[2], l[3]);
}

// --------------------------------- launch ----------------------------------
namespace {
// BYTES: (rows_A*2 + rows_B*2) * SP elems * 2 B/elem * NST stages
constexpr int SM_W = (2 * 128 + 2 * 128) * SP * 2 * NST;  // 81920 B -> 2 CTA/SM
constexpr int SM_A = (2 * 128 + 2 * 64) * SP * 2 * NST;   // 61440 B -> 3 CTA/SM
}

extern "C" void kernel_launch(void* const* d_in, const int* in_sizes, int n_in,
                              void* d_out, int out_size) {
    const int* tok = (const int*)d_in[0];
    const int* pos = (const int*)d_in[1];
    const float* emb = (const float*)d_in[2];
    const float* attn_nw = (const float*)d_in[3];
    const float* wq = (const float*)d_in[4];
    const float* wk = (const float*)d_in[5];
    const float* wv = (const float*)d_in[6];
    const float* wo = (const float*)d_in[7];
    const float* ff_nw = (const float*)d_in[8];
    const float* w1 = (const float*)d_in[9];
    const float* w2 = (const float*)d_in[10];
    const float* w3 = (const float*)d_in[11];
    const float* norm_w = (const float*)d_in[12];
    float* out = (float*)d_out;

    cudaFuncSetAttribute(gemm_t<128, 128, 2, 4, 2>, cudaFuncAttributeMaxDynamicSharedMemorySize, SM_W);
    cudaFuncSetAttribute(gemm_t<128, 64, 2, 2, 0>, cudaFuncAttributeMaxDynamicSharedMemorySize, SM_A);
    cudaFuncSetAttribute(gemm_t<128, 64, 2, 2, 1>, cudaFuncAttributeMaxDynamicSharedMemorySize, SM_A);
    cudaFuncSetAttribute(gemm_t<128, 64, 2, 2, 3>, cudaFuncAttributeMaxDynamicSharedMemorySize, SM_A);

    float *x, *qkv, *s, *f13;
    cudaGetSymbolAddress((void**)&x, g_x);
    cudaGetSymbolAddress((void**)&qkv, g_qkv);
    cudaGetSymbolAddress((void**)&s, g_s);
    cudaGetSymbolAddress((void**)&f13, g_f13);

    __nv_bfloat16 *hh[2], *oo[2], *gg[2], *pq[2], *pk[2], *pvt[2], *pp[2],
        *wqkv[2], *wwo[2], *w13[2], *ww2[2], *pemb[2];
    for (int si = 0; si < 2; si++) {
        cudaGetSymbolAddress((void**)&hh[si], c_h);
        cudaGetSymbolAddress((void**)&oo[si], c_o);
        cudaGetSymbolAddress((void**)&gg[si], c_g);
        cudaGetSymbolAddress((void**)&pq[si], b_q);
        cudaGetSymbolAddress((void**)&pk[si], b_k);
        cudaGetSymbolAddress((void**)&pvt[si], b_vt);
        cudaGetSymbolAddress((void**)&pp[si], b_p);
        cudaGetSymbolAddress((void**)&wqkv[si], c_wqkv);
        cudaGetSymbolAddress((void**)&wwo[si], c_wo);
        cudaGetSymbolAddress((void**)&w13[si], c_w13);
        cudaGetSymbolAddress((void**)&ww2[si], c_w2);
        cudaGetSymbolAddress((void**)&pemb[si], c_emb);
        hh[si] += (size_t)si * kBT * kD;
        oo[si] += (size_t)si * kBT * kD;
        gg[si] += (size_t)si * kBT * kDFF;
        pq[si] += (size_t)si * kBH * kT * kHD;
        pk[si] += (size_t)si * kBH * kT * kHD;
        pvt[si] += (size_t)si * kBH * kHD * kT;
        pp[si] += (size_t)si * kBH * kT * kT;
        wqkv[si] += (size_t)si * kL * 3 * kD * kD;
        wwo[si] += (size_t)si * kL * kD * kD;
        w13[si] += (size_t)si * kL * 2 * kDFF * kD;
        ww2[si] += (size_t)si * kL * kD * kDFF;
        pemb[si] += (size_t)si * kVOCAB * kD;
    }

    const int DD = kD * kD, FD = kDFF * kD;

    // Launch order: QKV weights GEMM at launch index 3 (ncu capture target).
    {   // 0: wq, wk, wv interleave into c_wqkv; wo contiguous
        CvtP p{};
        p.src[0] = wq; p.src[1] = wk; p.src[2] = wv; p.src[3] = wo;
        p.hi[0] = wqkv[0]; p.hi[1] = wqkv[0] + DD; p.hi[2] = wqkv[0] + 2 * DD; p.hi[3] = wwo[0];
        p.lo[0] = wqkv[1]; p.lo[1] = wqkv[1] + DD; p.lo[2] = wqkv[1] + 2 * DD; p.lo[3] = wwo[1];
        p.strideE[0] = p.strideE[1] = p.strideE[2] = 3LL * DD;
        p.strideE[3] = DD;
        p.n4 = kL * DD / 4; p.seg4 = DD / 4;
        cvt_batch<<<dim3(1024, 4), 256>>>(p);
    }
    embed_kernel<<<kBT, 256>>>(tok, emb);                   // 1
    rmsnorm_cvt<<<kBT, 256>>>(x, attn_nw, hh[0], hh[1]);    // 2 (layer 0)

    GemmP g{};
    g = GemmP{hh[0], hh[1], wqkv[0], wqkv[1],
              qkv, nullptr, nullptr, 0, DD, 1 << 20, 0, (long long)kBT * kD, kD, kD};
    gemm_t<128, 64, 2, 2, 0><<<dim3(16, 16, 3), 128, SM_A>>>(g);  // 3: ncu target

    {   // 4: w1, w3 interleave into c_w13; w2, emb contiguous
        CvtP p{};
        p.src[0] = w1; p.src[1] = w3; p.src[2] = w2; p.src[3] = emb;
        p.hi[0] = w13[0]; p.hi[1] = w13[0] + FD; p.hi[2] = ww2[0]; p.hi[3] = pemb[0];
        p.lo[0] = w13[1]; p.lo[1] = w13[1] + FD; p.lo[2] = ww2[1]; p.lo[3] = pemb[1];
        p.strideE[0] = p.strideE[1] = 2LL * FD;
        p.strideE[2] = FD; p.strideE[3] = FD;
        p.n4 = kL * FD / 4; p.seg4 = FD / 4;
        cvt_batch<<<dim3(2048, 4), 256>>>(p);
    }
    rope_init<<<1, 32>>>();                                 // 5

    for (int l = 0; l < kL; l++) {
        // --- attention ---
        if (l > 0) {
            rmsnorm_cvt<<<kBT, 256>>>(x, attn_nw + (size_t)l * kD, hh[0], hh[1]);
            g = GemmP{hh[0], hh[1], wqkv[0] + (size_t)l * 3 * DD, wqkv[1] + (size_t)l * 3 * DD,
                      qkv, nullptr, nullptr, 0, DD, 1 << 20, 0, (long long)kBT * kD, kD, kD};
            gemm_t<128, 64, 2, 2, 0><<<dim3(16, 16, 3), 128, SM_A>>>(g);
        }
        rope_cvt<<<kBT, 512>>>(pos);
        v_cvt<<<dim3(kT / 64, kBH), 256>>>();
        g = GemmP{pq[0], pq[1], pk[0], pk[1], s, nullptr, nullptr,
                  (long long)kT * kHD, (long long)kT * kHD,
                  1 << 20, 0, (long long)kT * kT, kHD, kT};
        gemm_t<128, 128, 2, 4, 2><<<dim3(8, 8, kBH), 256, SM_W>>>(g);
        softmax_cvt<<<kBH * kT, 256>>>();
        g = GemmP{pp[0], pp[1], pvt[0], pvt[1], nullptr, oo[0], oo[1],
                  (long long)kT * kT, (long long)kHD * kT,
                  kH, (long long)kT * kD, kHD, kT, kD};
        gemm_t<128, 64, 2, 2, 3><<<dim3(1, 8, kBH), 128, SM_A>>>(g);
        g = GemmP{oo[0], oo[1], wwo[0] + (size_t)l * DD, wwo[1] + (size_t)l * DD,
                  x, nullptr, nullptr, 0, 0, 1 << 20, 0, 0, kD, kD};
        gemm_t<128, 64, 2, 2, 1><<<dim3(16, 16, 1), 128, SM_A>>>(g);
        // --- FFN ---
        rmsnorm_cvt<<<kBT, 256>>>(x, ff_nw + (size_t)l * kD, hh[0], hh[1]);
        g = GemmP{hh[0], hh[1], w13[0] + (size_t)l * 2 * FD, w13[1] + (size_t)l * 2 * FD,
                  f13, nullptr, nullptr, 0, FD, 1 << 20, 0, (long long)kBT * kDFF, kD, kDFF};
        gemm_t<128, 64, 2, 2, 0><<<dim3(64, 16, 2), 128, SM_A>>>(g);
        silu_cvt<<<kBT * kDFF / 1024, 256>>>();
        g = GemmP{gg[0], gg[1], ww2[0] + (size_t)l * kD * kDFF, ww2[1] + (size_t)l * kD * kDFF,
                  x, nullptr, nullptr, 0, 0, 1 << 20, 0, 0, kDFF, kD};
        gemm_t<128, 64, 2, 2, 1><<<dim3(16, 16, 1), 128, SM_A>>>(g);
    }

    // --- final norm + tied LM head ---
    rmsnorm_cvt<<<kBT, 256>>>(x, norm_w, hh[0], hh[1]);
    g = GemmP{hh[0], hh[1], pemb[0], pemb[1], out, nullptr, nullptr,
              0, 0, 1 << 20, 0, 0, kD, kVOCAB};
    gemm_t<128, 64, 2, 2, 0><<<dim3(kVOCAB / 64, 16, 1), 128, SM_A>>>(g);
}

// round 13
// speedup vs baseline: 1.2396x; 1.2396x over previous
#include <cuda_runtime.h>
#include <cuda_bf16.h>
#include <cuda_fp16.h>
#include <cstdint>
#include <math.h>

namespace {
constexpr int kB = 2, kT = 1024, kD = 1024, kH = 16, kHD = 64, kL = 4;
constexpr int kDFF = 4096, kVOCAB = 16384;
constexpr int kBT = kB * kT;
constexpr int kBH = kB * kH;
constexpr float kEPS = 1e-6f;
constexpr int KC = 32;     // k-chunk
constexpr int SP = 40;     // padded smem row stride (16-bit elems)
constexpr int NST = 2;     // pipeline stages
}

// ------------------------- static device scratch ---------------------------
__device__ float g_x[kBT * kD];
__device__ float g_qkv[3 * kBT * kD];
__device__ float g_s[(size_t)kBH * kT * kT];
__device__ float g_f13[2 * kBT * kDFF];
__device__ float g_inv[32];

// bf16 3-pass path (QKV + attention)
__device__ __nv_bfloat16 c_h[2][kBT * kD];
__device__ __nv_bfloat16 b_q[2][kBH * kT * kHD];
__device__ __nv_bfloat16 b_k[2][kBH * kT * kHD];
__device__ __nv_bfloat16 b_vt[2][kBH * kHD * kT];
__device__ __nv_bfloat16 b_p[2][(size_t)kBH * kT * kT];
__device__ __nv_bfloat16 c_wqkv[2][kL * 3 * kD * kD];

// fp16 2-pass path (wo / w13 / w2 / LM head)
__device__ __half h_o[kBT * kD];          // attention output (single fp16)
__device__ __half h_h[kBT * kD];          // ffn/final normed activations
__device__ __half h_g[kBT * kDFF];        // silu output
__device__ __half h_wo[2][kL * kD * kD];
__device__ __half h_w13[2][kL * 2 * kDFF * kD];
__device__ __half h_w2[2][kL * kD * kDFF];
__device__ __half h_emb[2][kVOCAB * kD];

// ------------------------------ PTX helpers --------------------------------
__device__ __forceinline__ uint32_t smem_u32(const void* p) {
    uint32_t a;
    asm("{ .reg .u64 t; cvta.to.shared.u64 t, %1; cvt.u32.u64 %0, t; }" : "=r"(a) : "l"(p));
    return a;
}
__device__ __forceinline__ void cp16(uint32_t dst, const void* src) {
    asm volatile("cp.async.cg.shared.global [%0], [%1], 16;" :: "r"(dst), "l"(src));
}
__device__ __forceinline__ void cp_commit() { asm volatile("cp.async.commit_group;" ::: "memory"); }
__device__ __forceinline__ void cp_wait0() { asm volatile("cp.async.wait_group 0;" ::: "memory"); }

__device__ __forceinline__ void ldsm4(uint32_t& r0, uint32_t& r1, uint32_t& r2, uint32_t& r3,
                                      uint32_t addr) {
    asm volatile("ldmatrix.sync.aligned.m8n8.x4.shared.b16 {%0,%1,%2,%3},[%4];"
                 : "=r"(r0), "=r"(r1), "=r"(r2), "=r"(r3) : "r"(addr));
}
__device__ __forceinline__ void mma_bf16(float* c, const uint32_t* A, const uint32_t* B) {
    asm volatile(
        "mma.sync.aligned.m16n8k16.row.col.f32.bf16.bf16.f32 "
        "{%0,%1,%2,%3},{%4,%5,%6,%7},{%8,%9},{%0,%1,%2,%3};"
        : "+f"(c[0]), "+f"(c[1]), "+f"(c[2]), "+f"(c[3])
        : "r"(A[0]), "r"(A[1]), "r"(A[2]), "r"(A[3]), "r"(B[0]), "r"(B[1]));
}
__device__ __forceinline__ void mma_f16(float* c, const uint32_t* A, const uint32_t* B) {
    asm volatile(
        "mma.sync.aligned.m16n8k16.row.col.f32.f16.f16.f32 "
        "{%0,%1,%2,%3},{%4,%5,%6,%7},{%8,%9},{%0,%1,%2,%3};"
        : "+f"(c[0]), "+f"(c[1]), "+f"(c[2]), "+f"(c[3])
        : "r"(A[0]), "r"(A[1]), "r"(A[2]), "r"(A[3]), "r"(B[0]), "r"(B[1]));
}
__device__ __forceinline__ void split_bf16(float f, __nv_bfloat16& hi, __nv_bfloat16& lo) {
    hi = __float2bfloat16(f);
    lo = __float2bfloat16(f - __bfloat162float(hi));
}
__device__ __forceinline__ void split_f16(float f, __half& hi, __half& lo) {
    hi = __float2half(f);
    lo = __float2half(f - __half2float(hi));
}

// ------------- batched fp32 -> (hi,lo) bf16 converter (z-indexed) ----------
struct CvtP {
    const float* src[4];
    __nv_bfloat16 *hi[4], *lo[4];
    long long strideE[4];
    int n4, seg4;
};

__global__ void cvt_batch(CvtP p) {
    const int z = blockIdx.y;
    const float4* src = reinterpret_cast<const float4*>(p.src[z]);
    __nv_bfloat16* hi = p.hi[z];
    __nv_bfloat16* lo = p.lo[z];
    const long long strE = p.strideE[z];
    const int stride = gridDim.x * blockDim.x;
    for (int i = blockIdx.x * blockDim.x + threadIdx.x; i < p.n4; i += stride) {
        float4 v = src[i];
        int l = i / p.seg4, r = i - l * p.seg4;
        long long d = (long long)l * strE + (long long)r * 4;
        __nv_bfloat16 h0, h1, h2, h3, l0, l1, l2, l3;
        split_bf16(v.x, h0, l0); split_bf16(v.y, h1, l1);
        split_bf16(v.z, h2, l2); split_bf16(v.w, h3, l3);
        *reinterpret_cast<__nv_bfloat162*>(hi + d)     = __nv_bfloat162(h0, h1);
        *reinterpret_cast<__nv_bfloat162*>(hi + d + 2) = __nv_bfloat162(h2, h3);
        *reinterpret_cast<__nv_bfloat162*>(lo + d)     = __nv_bfloat162(l0, l1);
        *reinterpret_cast<__nv_bfloat162*>(lo + d + 2) = __nv_bfloat162(l2, l3);
    }
}

// ------------- batched fp32 -> (hi,lo) fp16 converter (z-indexed) ----------
struct CvtHP {
    const float* src[4];
    __half *hi[4], *lo[4];
    long long strideE[4];
    int n4, seg4;
};

__global__ void cvt_batch_h(CvtHP p) {
    const int z = blockIdx.y;
    const float4* src = reinterpret_cast<const float4*>(p.src[z]);
    __half* hi = p.hi[z];
    __half* lo = p.lo[z];
    const long long strE = p.strideE[z];
    const int stride = gridDim.x * blockDim.x;
    for (int i = blockIdx.x * blockDim.x + threadIdx.x; i < p.n4; i += stride) {
        float4 v = src[i];
        int l = i / p.seg4, r = i - l * p.seg4;
        long long d = (long long)l * strE + (long long)r * 4;
        __half h0, h1, h2, h3, l0, l1, l2, l3;
        split_f16(v.x, h0, l0); split_f16(v.y, h1, l1);
        split_f16(v.z, h2, l2); split_f16(v.w, h3, l3);
        *reinterpret_cast<__half2*>(hi + d)     = __half2(h0, h1);
        *reinterpret_cast<__half2*>(hi + d + 2) = __half2(h2, h3);
        *reinterpret_cast<__half2*>(lo + d)     = __half2(l0, l1);
        *reinterpret_cast<__half2*>(lo + d + 2) = __half2(l2, l3);
    }
}

// ------ bf16 3-pass GEMM (QKV + attention): C[M,N] = A*B^T -----------------
// EPI: 0 = fp32 store, 2 = fp32 store *0.125, 4 = single fp16 store (to Ch).
struct GemmP {
    const __nv_bfloat16 *Ah, *Al, *Bh, *Bl;
    float* C;
    __half* Ch;
    long long strA, strB;
    int czDiv; long long czOut, czIn;
    int K, ldC;
};

template <int BM_, int BN_, int WR, int WC, int EPI>
__global__ void __launch_bounds__(WR * WC * 32, (WR * WC * 32) <= 128 ? 3 : 2)
gemm_t(GemmP a) {
    constexpr int NT = WR * WC * 32;
    constexpr int ST_AH = 0, ST_AL = BM_ * SP;
    constexpr int ST_BH = 2 * BM_ * SP, ST_BL = 2 * BM_ * SP + BN_ * SP;
    constexpr int SE = 2 * BM_ * SP + 2 * BN_ * SP;
    extern __shared__ __nv_bfloat16 sm[];

    const int tid = threadIdx.x;
    const int w = tid >> 5, lane = tid & 31;
    const int wm = w / WC, wn = w % WC;
    const int K = a.K;
    const int bm = blockIdx.y * BM_, bn = blockIdx.x * BN_;
    const int z = blockIdx.z;

    const long long cOff = (long long)(z / a.czDiv) * a.czOut +
                           (long long)(z % a.czDiv) * a.czIn;
    const __nv_bfloat16* Ahg = a.Ah + (long long)z * a.strA + (long long)bm * K;
    const __nv_bfloat16* Alg = a.Al + (long long)z * a.strA + (long long)bm * K;
    const __nv_bfloat16* Bhg = a.Bh + (long long)z * a.strB + (long long)bn * K;
    const __nv_bfloat16* Blg = a.Bl + (long long)z * a.strB + (long long)bn * K;

    float acc[4][4][4];
#pragma unroll
    for (int i = 0; i < 4; i++)
#pragma unroll
        for (int j = 0; j < 4; j++)
#pragma unroll
            for (int q = 0; q < 4; q++) acc[i][j][q] = 0.f;

    auto load_chunk = [&](int st, int kt) {
        __nv_bfloat16* s = sm + st * SE;
        const int kof = kt * KC;
#pragma unroll 2
        for (int idx = tid; idx < BM_ * 4; idx += NT) {
            int row = idx >> 2, sg = idx & 3;
            long long go = (long long)row * K + kof + sg * 8;
            cp16(smem_u32(s + ST_AH + row * SP + sg * 8), Ahg + go);
            cp16(smem_u32(s + ST_AL + row * SP + sg * 8), Alg + go);
        }
#pragma unroll 2
        for (int idx = tid; idx < BN_ * 4; idx += NT) {
            int row = idx >> 2, sg = idx & 3;
            long long go = (long long)row * K + kof + sg * 8;
            cp16(smem_u32(s + ST_BH + row * SP + sg * 8), Bhg + go);
            cp16(smem_u32(s + ST_BL + row * SP + sg * 8), Blg + go);
        }
        cp_commit();
    };

    const int a_row = wm * 64 + (lane & 15);
    const int a_kof = (lane >> 4) * 8;
    const int b_row = wn * 32 + (lane >> 4) * 8 + (lane & 7);
    const int b_kof = ((lane >> 3) & 1) * 8;

    const int nch = K / KC;
    load_chunk(0, 0);

    for (int kt = 0; kt < nch; kt++) {
        cp_wait0();
        __syncthreads();
        if (kt + 1 < nch) load_chunk((kt + 1) & 1, kt + 1);

        const __nv_bfloat16* s = sm + (kt & 1) * SE;
#pragma unroll
        for (int k16 = 0; k16 < KC / 16; k16++) {
            const int kk = k16 * 16;
            uint32_t af[4][4], bh_[4][2], bl_[4][2];
#pragma unroll
            for (int nt = 0; nt < 2; nt++) {
                ldsm4(bh_[2 * nt][0], bh_[2 * nt][1], bh_[2 * nt + 1][0], bh_[2 * nt + 1][1],
                      smem_u32(s + ST_BH + (b_row + nt * 16) * SP + b_kof + kk));
                ldsm4(bl_[2 * nt][0], bl_[2 * nt][1], bl_[2 * nt + 1][0], bl_[2 * nt + 1][1],
                      smem_u32(s + ST_BL + (b_row + nt * 16) * SP + b_kof + kk));
            }
#pragma unroll
            for (int mi = 0; mi < 4; mi++)
                ldsm4(af[mi][0], af[mi][1], af[mi][2], af[mi][3],
                      smem_u32(s + ST_AH + (a_row + mi * 16) * SP + a_kof + kk));
#pragma unroll
            for (int mi = 0; mi < 4; mi++)
#pragma unroll
                for (int ni = 0; ni < 4; ni++) mma_bf16(acc[mi][ni], af[mi], bh_[ni]);
#pragma unroll
            for (int mi = 0; mi < 4; mi++)
#pragma unroll
                for (int ni = 0; ni < 4; ni++) mma_bf16(acc[mi][ni], af[mi], bl_[ni]);
#pragma unroll
            for (int mi = 0; mi < 4; mi++)
                ldsm4(af[mi][0], af[mi][1], af[mi][2], af[mi][3],
                      smem_u32(s + ST_AL + (a_row + mi * 16) * SP + a_kof + kk));
#pragma unroll
            for (int mi = 0; mi < 4; mi++)
#pragma unroll
                for (int ni = 0; ni < 4; ni++) mma_bf16(acc[mi][ni], af[mi], bh_[ni]);
        }
    }

    const int ldC = a.ldC;
#pragma unroll
    for (int mi = 0; mi < 4; mi++) {
#pragma unroll
        for (int ni = 0; ni < 4; ni++) {
            int row0 = bm + wm * 64 + mi * 16 + (lane >> 2);
            int col = bn + wn * 32 + ni * 8 + (lane & 3) * 2;
            long long o0 = cOff + (long long)row0 * ldC + col;
            long long o1 = cOff + (long long)(row0 + 8) * ldC + col;
            if (EPI == 4) {
                *reinterpret_cast<__half2*>(a.Ch + o0) =
                    __half2(__float2half(acc[mi][ni][0]), __float2half(acc[mi][ni][1]));
                *reinterpret_cast<__half2*>(a.Ch + o1) =
                    __half2(__float2half(acc[mi][ni][2]), __float2half(acc[mi][ni][3]));
            } else {
                float sc = (EPI == 2) ? 0.125f : 1.f;
                *reinterpret_cast<float2*>(a.C + o0) =
                    make_float2(acc[mi][ni][0] * sc, acc[mi][ni][1] * sc);
                *reinterpret_cast<float2*>(a.C + o1) =
                    make_float2(acc[mi][ni][2] * sc, acc[mi][ni][3] * sc);
            }
        }
    }
}

// ------ fp16 2-pass GEMM (wo/w13/w2/LM): C = A * (Bh+Bl)^T -----------------
// A single fp16, B fp16 hi/lo. EPI: 0 = fp32 store, 1 = fp32 add.
struct GemmHP {
    const __half *A, *Bh, *Bl;
    float* C;
    long long strB;
    int czDiv; long long czOut, czIn;
    int K, ldC;
};

template <int BM_, int BN_, int WR, int WC, int EPI>
__global__ void __launch_bounds__(WR * WC * 32, 3) gemm_h2(GemmHP a) {
    constexpr int NT = WR * WC * 32;
    constexpr int ST_A = 0, ST_BH = BM_ * SP, ST_BL = (BM_ + BN_) * SP;
    constexpr int SE = (BM_ + 2 * BN_) * SP;
    extern __shared__ __half smh[];

    const int tid = threadIdx.x;
    const int w = tid >> 5, lane = tid & 31;
    const int wm = w / WC, wn = w % WC;
    const int K = a.K;
    const int bm = blockIdx.y * BM_, bn = blockIdx.x * BN_;
    const int z = blockIdx.z;

    const long long cOff = (long long)(z / a.czDiv) * a.czOut +
                           (long long)(z % a.czDiv) * a.czIn;
    const __half* Ag = a.A + (long long)z * 0 + (long long)bm * K;
    const __half* Bhg = a.Bh + (long long)z * a.strB + (long long)bn * K;
    const __half* Blg = a.Bl + (long long)z * a.strB + (long long)bn * K;

    float acc[4][4][4];
#pragma unroll
    for (int i = 0; i < 4; i++)
#pragma unroll
        for (int j = 0; j < 4; j++)
#pragma unroll
            for (int q = 0; q < 4; q++) acc[i][j][q] = 0.f;

    auto load_chunk = [&](int st, int kt) {
        __half* s = smh + st * SE;
        const int kof = kt * KC;
#pragma unroll 2
        for (int idx = tid; idx < BM_ * 4; idx += NT) {
            int row = idx >> 2, sg = idx & 3;
            cp16(smem_u32(s + ST_A + row * SP + sg * 8),
                 Ag + (long long)row * K + kof + sg * 8);
        }
#pragma unroll 2
        for (int idx = tid; idx < BN_ * 4; idx += NT) {
            int row = idx >> 2, sg = idx & 3;
            long long go = (long long)row * K + kof + sg * 8;
            cp16(smem_u32(s + ST_BH + row * SP + sg * 8), Bhg + go);
            cp16(smem_u32(s + ST_BL + row * SP + sg * 8), Blg + go);
        }
        cp_commit();
    };

    const int a_row = wm * 64 + (lane & 15);
    const int a_kof = (lane >> 4) * 8;
    const int b_row = wn * 32 + (lane >> 4) * 8 + (lane & 7);
    const int b_kof = ((lane >> 3) & 1) * 8;

    const int nch = K / KC;
    load_chunk(0, 0);

    for (int kt = 0; kt < nch; kt++) {
        cp_wait0();
        __syncthreads();
        if (kt + 1 < nch) load_chunk((kt + 1) & 1, kt + 1);

        const __half* s = smh + (kt & 1) * SE;
#pragma unroll
        for (int k16 = 0; k16 < KC / 16; k16++) {
            const int kk = k16 * 16;
            uint32_t af[4][4], bh_[4][2], bl_[4][2];
#pragma unroll
            for (int nt = 0; nt < 2; nt++) {
                ldsm4(bh_[2 * nt][0], bh_[2 * nt][1], bh_[2 * nt + 1][0], bh_[2 * nt + 1][1],
                      smem_u32(s + ST_BH + (b_row + nt * 16) * SP + b_kof + kk));
                ldsm4(bl_[2 * nt][0], bl_[2 * nt][1], bl_[2 * nt + 1][0], bl_[2 * nt + 1][1],
                      smem_u32(s + ST_BL + (b_row + nt * 16) * SP + b_kof + kk));
            }
#pragma unroll
            for (int mi = 0; mi < 4; mi++)
                ldsm4(af[mi][0], af[mi][1], af[mi][2], af[mi][3],
                      smem_u32(s + ST_A + (a_row + mi * 16) * SP + a_kof + kk));
#pragma unroll
            for (int mi = 0; mi < 4; mi++)
#pragma unroll
                for (int ni = 0; ni < 4; ni++) mma_f16(acc[mi][ni], af[mi], bh_[ni]);
#pragma unroll
            for (int mi = 0; mi < 4; mi++)
#pragma unroll
                for (int ni = 0; ni < 4; ni++) mma_f16(acc[mi][ni], af[mi], bl_[ni]);
        }
    }

    const int ldC = a.ldC;
#pragma unroll
    for (int mi = 0; mi < 4; mi++) {
#pragma unroll
        for (int ni = 0; ni < 4; ni++) {
            int row0 = bm + wm * 64 + mi * 16 + (lane >> 2);
            int col = bn + wn * 32 + ni * 8 + (lane & 3) * 2;
            long long o0 = cOff + (long long)row0 * ldC + col;
            long long o1 = cOff + (long long)(row0 + 8) * ldC + col;
            float2 v0 = make_float2(acc[mi][ni][0], acc[mi][ni][1]);
            float2 v1 = make_float2(acc[mi][ni][2], acc[mi][ni][3]);
            if (EPI == 1) {
                float2 p0 = *reinterpret_cast<const float2*>(a.C + o0);
                float2 p1 = *reinterpret_cast<const float2*>(a.C + o1);
                v0.x += p0.x; v0.y += p0.y; v1.x += p1.x; v1.y += p1.y;
            }
            *reinterpret_cast<float2*>(a.C + o0) = v0;
            *reinterpret_cast<float2*>(a.C + o1) = v1;
        }
    }
}

// ------------------------------- elementwise -------------------------------
__global__ void embed_kernel(const int* __restrict__ tok, const float* __restrict__ emb) {
    int row = blockIdx.x;
    const float4* src = reinterpret_cast<const float4*>(emb + (size_t)tok[row] * kD);
    float4* dst = reinterpret_cast<float4*>(g_x + (size_t)row * kD);
    for (int i = threadIdx.x; i < kD / 4; i += blockDim.x) dst[i] = src[i];
}

// RMSNorm -> bf16 hi/lo (attention path)
__global__ void rmsnorm_cvt(const float* __restrict__ in, const float* __restrict__ w,
                            __nv_bfloat16* __restrict__ oh, __nv_bfloat16* __restrict__ ol) {
    int row = blockIdx.x, tid = threadIdx.x;
    float4 v = reinterpret_cast<const float4*>(in + (size_t)row * kD)[tid];
    __shared__ float red[256];
    red[tid] = v.x * v.x + v.y * v.y + v.z * v.z + v.w * v.w;
    __syncthreads();
    for (int off = 128; off > 0; off >>= 1) {
        if (tid < off) red[tid] += red[tid + off];
        __syncthreads();
    }
    float inv = rsqrtf(red[0] * (1.f / kD) + kEPS);
    float4 wv = reinterpret_cast<const float4*>(w)[tid];
    float y[4] = {v.x * inv * wv.x, v.y * inv * wv.y, v.z * inv * wv.z, v.w * inv * wv.w};
    __nv_bfloat16 h[4], l[4];
#pragma unroll
    for (int j = 0; j < 4; j++) split_bf16(y[j], h[j], l[j]);
    size_t o = (size_t)row * kD + tid * 4;
    reinterpret_cast<__nv_bfloat162*>(oh + o)[0] = __nv_bfloat162(h[0], h[1]);
    reinterpret_cast<__nv_bfloat162*>(oh + o)[1] = __nv_bfloat162(h[2], h[3]);
    reinterpret_cast<__nv_bfloat162*>(ol + o)[0] = __nv_bfloat162(l[0], l[1]);
    reinterpret_cast<__nv_bfloat162*>(ol + o)[1] = __nv_bfloat162(l[2], l[3]);
}

// RMSNorm -> single fp16 (ffn / lm-head path)
__global__ void rmsnorm_cvt16(const float* __restrict__ in, const float* __restrict__ w,
                              __half* __restrict__ oh) {
    int row = blockIdx.x, tid = threadIdx.x;
    float4 v = reinterpret_cast<const float4*>(in + (size_t)row * kD)[tid];
    __shared__ float red[256];
    red[tid] = v.x * v.x + v.y * v.y + v.z * v.z + v.w * v.w;
    __syncthreads();
    for (int off = 128; off > 0; off >>= 1) {
        if (tid < off) red[tid] += red[tid + off];
        __syncthreads();
    }
    float inv = rsqrtf(red[0] * (1.f / kD) + kEPS);
    float4 wv = reinterpret_cast<const float4*>(w)[tid];
    size_t o = (size_t)row * kD + tid * 4;
    reinterpret_cast<__half2*>(oh + o)[0] =
        __half2(__float2half(v.x * inv * wv.x), __float2half(v.y * inv * wv.y));
    reinterpret_cast<__half2*>(oh + o)[1] =
        __half2(__float2half(v.z * inv * wv.z), __float2half(v.w * inv * wv.w));
}

__global__ void rope_init() {
    int i = threadIdx.x;
    if (i < 32) g_inv[i] = (float)(1.0 / pow(10000.0, (double)(2 * i) / (double)kHD));
}

__global__ void rope_cvt(const int* __restrict__ pos) {
    int row = blockIdx.x, idx = threadIdx.x;
    int h = idx >> 5, i = idx & 31;
    int b = row >> 10, t = row & 1023;
    float ang = (float)pos[row] * g_inv[i];
    float s, c;
    sincosf(ang, &s, &c);
    const float* qs = g_qkv + (size_t)row * kD + h * kHD + 2 * i;
    const float* ks = qs + (size_t)kBT * kD;
    float qr = qs[0], qi = qs[1], kr = ks[0], ki = ks[1];
    float q0 = qr * c - qi * s, q1 = qr * s + qi * c;
    float k0 = kr * c - ki * s, k1 = kr * s + ki * c;
    size_t dst = ((size_t)(b * kH + h) * kT + t) * kHD + 2 * i;
    __nv_bfloat16 h0, h1, l0, l1;
    split_bf16(q0, h0, l0); split_bf16(q1, h1, l1);
    *reinterpret_cast<__nv_bfloat162*>(&b_q[0][dst]) = __nv_bfloat162(h0, h1);
    *reinterpret_cast<__nv_bfloat162*>(&b_q[1][dst]) = __nv_bfloat162(l0, l1);
    split_bf16(k0, h0, l0); split_bf16(k1, h1, l1);
    *reinterpret_cast<__nv_bfloat162*>(&b_k[0][dst]) = __nv_bfloat162(h0, h1);
    *reinterpret_cast<__nv_bfloat162*>(&b_k[1][dst]) = __nv_bfloat162(l0, l1);
}

__global__ void v_cvt() {
    __shared__ float vs[64][65];
    int bh = blockIdx.y, b = bh >> 4, h = bh & 15;
    int t0 = blockIdx.x * 64;
    const float* src = g_qkv + 2LL * kBT * kD + ((size_t)(b * kT + t0)) * kD + h * kHD;
#pragma unroll
    for (int it = 0; it < 16; it++) {
        int e = it * 256 + threadIdx.x;
        int tr = e >> 6, hd = e & 63;
        vs[tr][hd] = src[(size_t)tr * kD + hd];
    }
    __syncthreads();
#pragma unroll
    for (int it = 0; it < 16; it++) {
        int e = it * 256 + threadIdx.x;
        int hd = e >> 6, tc = e & 63;
        __nv_bfloat16 hi, lo;
        split_bf16(vs[tc][hd], hi, lo);
        size_t dst = ((size_t)bh * kHD + hd) * kT + t0 + tc;
        b_vt[0][dst] = hi;
        b_vt[1][dst] = lo;
    }
}

__global__ void softmax_cvt() {
    size_t row = blockIdx.x;
    const float* p = g_s + row * (size_t)kT;
    __shared__ float red[256];
    int tid = threadIdx.x;
    float v[4], m = -1e30f;
#pragma unroll
    for (int j = 0; j < 4; j++) { v[j] = p[tid + j * 256]; m = fmaxf(m, v[j]); }
    red[tid] = m;
    __syncthreads();
    for (int off = 128; off > 0; off >>= 1) {
        if (tid < off) red[tid] = fmaxf(red[tid], red[tid + off]);
        __syncthreads();
    }
    float M = red[0];
    __syncthreads();
    float sum = 0.f;
#pragma unroll
    for (int j = 0; j < 4; j++) { v[j] = expf(v[j] - M); sum += v[j]; }
    red[tid] = sum;
    __syncthreads();
    for (int off = 128; off > 0; off >>= 1) {
        if (tid < off) red[tid] += red[tid + off];
        __syncthreads();
    }
    float inv = 1.f / red[0];
#pragma unroll
    for (int j = 0; j < 4; j++) {
        __nv_bfloat16 hi, lo;
        split_bf16(v[j] * inv, hi, lo);
        size_t o = row * kT + tid + j * 256;
        b_p[0][o] = hi;
        b_p[1][o] = lo;
    }
}

__global__ void silu_cvt16() {
    int i4 = blockIdx.x * 256 + threadIdx.x;
    float4 a = reinterpret_cast<const float4*>(g_f13)[i4];
    float4 b = reinterpret_cast<const float4*>(g_f13)[i4 + kBT * kDFF / 4];
    size_t o = (size_t)i4 * 4;
    reinterpret_cast<__half2*>(h_g + o)[0] =
        __half2(__float2half(a.x / (1.f + expf(-a.x)) * b.x),
                __float2half(a.y / (1.f + expf(-a.y)) * b.y));
    reinterpret_cast<__half2*>(h_g + o)[1] =
        __half2(__float2half(a.z / (1.f + expf(-a.z)) * b.z),
                __float2half(a.w / (1.f + expf(-a.w)) * b.w));
}

// --------------------------------- launch ----------------------------------
namespace {
constexpr int SM_W = (2 * 128 + 2 * 128) * SP * 2 * NST;  // 81920 B (bf16 scores)
constexpr int SM_A = (2 * 128 + 2 * 64) * SP * 2 * NST;   // 61440 B (bf16 3-pass)
constexpr int SM_H = (128 + 2 * 64) * SP * 2 * NST;       // 40960 B (fp16 2-pass)
}

extern "C" void kernel_launch(void* const* d_in, const int* in_sizes, int n_in,
                              void* d_out, int out_size) {
    const int* tok = (const int*)d_in[0];
    const int* pos = (const int*)d_in[1];
    const float* emb = (const float*)d_in[2];
    const float* attn_nw = (const float*)d_in[3];
    const float* wq = (const float*)d_in[4];
    const float* wk = (const float*)d_in[5];
    const float* wv = (const float*)d_in[6];
    const float* wo = (const float*)d_in[7];
    const float* ff_nw = (const float*)d_in[8];
    const float* w1 = (const float*)d_in[9];
    const float* w2 = (const float*)d_in[10];
    const float* w3 = (const float*)d_in[11];
    const float* norm_w = (const float*)d_in[12];
    float* out = (float*)d_out;

    cudaFuncSetAttribute(gemm_t<128, 128, 2, 4, 2>, cudaFuncAttributeMaxDynamicSharedMemorySize, SM_W);
    cudaFuncSetAttribute(gemm_t<128, 64, 2, 2, 0>, cudaFuncAttributeMaxDynamicSharedMemorySize, SM_A);
    cudaFuncSetAttribute(gemm_t<128, 64, 2, 2, 4>, cudaFuncAttributeMaxDynamicSharedMemorySize, SM_A);
    cudaFuncSetAttribute(gemm_h2<128, 64, 2, 2, 0>, cudaFuncAttributeMaxDynamicSharedMemorySize, SM_H);
    cudaFuncSetAttribute(gemm_h2<128, 64, 2, 2, 1>, cudaFuncAttributeMaxDynamicSharedMemorySize, SM_H);

    float *x, *qkv, *s, *f13;
    cudaGetSymbolAddress((void**)&x, g_x);
    cudaGetSymbolAddress((void**)&qkv, g_qkv);
    cudaGetSymbolAddress((void**)&s, g_s);
    cudaGetSymbolAddress((void**)&f13, g_f13);

    __nv_bfloat16 *hh[2], *pq[2], *pk[2], *pvt[2], *pp[2], *wqkv[2];
    for (int si = 0; si < 2; si++) {
        cudaGetSymbolAddress((void**)&hh[si], c_h);
        cudaGetSymbolAddress((void**)&pq[si], b_q);
        cudaGetSymbolAddress((void**)&pk[si], b_k);
        cudaGetSymbolAddress((void**)&pvt[si], b_vt);
        cudaGetSymbolAddress((void**)&pp[si], b_p);
        cudaGetSymbolAddress((void**)&wqkv[si], c_wqkv);
        hh[si] += (size_t)si * kBT * kD;
        pq[si] += (size_t)si * kBH * kT * kHD;
        pk[si] += (size_t)si * kBH * kT * kHD;
        pvt[si] += (size_t)si * kBH * kHD * kT;
        pp[si] += (size_t)si * kBH * kT * kT;
        wqkv[si] += (size_t)si * kL * 3 * kD * kD;
    }
    __half *po, *ph, *pg, *pwo[2], *pw13[2], *pw2[2], *pemb[2];
    cudaGetSymbolAddress((void**)&po, h_o);
    cudaGetSymbolAddress((void**)&ph, h_h);
    cudaGetSymbolAddress((void**)&pg, h_g);
    for (int si = 0; si < 2; si++) {
        cudaGetSymbolAddress((void**)&pwo[si], h_wo);
        cudaGetSymbolAddress((void**)&pw13[si], h_w13);
        cudaGetSymbolAddress((void**)&pw2[si], h_w2);
        cudaGetSymbolAddress((void**)&pemb[si], h_emb);
        pwo[si] += (size_t)si * kL * kD * kD;
        pw13[si] += (size_t)si * kL * 2 * kDFF * kD;
        pw2[si] += (size_t)si * kL * kD * kDFF;
        pemb[si] += (size_t)si * kVOCAB * kD;
    }

    const int DD = kD * kD, FD = kDFF * kD;

    // 0: wq/wk/wv -> bf16 hi/lo interleaved into c_wqkv
    {
        CvtP p{};
        p.src[0] = wq; p.src[1] = wk; p.src[2] = wv; p.src[3] = wq;
        p.hi[0] = wqkv[0]; p.hi[1] = wqkv[0] + DD; p.hi[2] = wqkv[0] + 2 * DD; p.hi[3] = wqkv[0];
        p.lo[0] = wqkv[1]; p.lo[1] = wqkv[1] + DD; p.lo[2] = wqkv[1] + 2 * DD; p.lo[3] = wqkv[1];
        p.strideE[0] = p.strideE[1] = p.strideE[2] = p.strideE[3] = 3LL * DD;
        p.n4 = kL * DD / 4; p.seg4 = DD / 4;
        cvt_batch<<<dim3(1024, 3), 256>>>(p);
    }
    embed_kernel<<<kBT, 256>>>(tok, emb);                   // 1
    rmsnorm_cvt<<<kBT, 256>>>(x, attn_nw, hh[0], hh[1]);    // 2

    GemmP g{};
    g = GemmP{hh[0], hh[1], wqkv[0], wqkv[1],
              qkv, nullptr, 0, DD, 1 << 20, 0, (long long)kBT * kD, kD, kD};
    gemm_t<128, 64, 2, 2, 0><<<dim3(16, 16, 3), 128, SM_A>>>(g);  // 3: ncu target

    {   // 4: w1,w3 interleave; w2, emb contiguous -> fp16 hi/lo
        CvtHP p{};
        p.src[0] = w1; p.src[1] = w3; p.src[2] = w2; p.src[3] = emb;
        p.hi[0] = pw13[0]; p.hi[1] = pw13[0] + FD; p.hi[2] = pw2[0]; p.hi[3] = pemb[0];
        p.lo[0] = pw13[1]; p.lo[1] = pw13[1] + FD; p.lo[2] = pw2[1]; p.lo[3] = pemb[1];
        p.strideE[0] = p.strideE[1] = 2LL * FD;
        p.strideE[2] = FD; p.strideE[3] = FD;
        p.n4 = kL * FD / 4; p.seg4 = FD / 4;
        cvt_batch_h<<<dim3(2048, 4), 256>>>(p);
    }
    {   // 5: wo -> fp16 hi/lo
        CvtHP p{};
        p.src[0] = wo; p.hi[0] = pwo[0]; p.lo[0] = pwo[1];
        p.strideE[0] = DD;
        p.n4 = kL * DD / 4; p.seg4 = DD / 4;
        cvt_batch_h<<<dim3(512, 1), 256>>>(p);
    }
    rope_init<<<1, 32>>>();                                 // 6

    GemmHP gh{};
    for (int l = 0; l < kL; l++) {
        if (l > 0) {
            rmsnorm_cvt<<<kBT, 256>>>(x, attn_nw + (size_t)l * kD, hh[0], hh[1]);
            g = GemmP{hh[0], hh[1], wqkv[0] + (size_t)l * 3 * DD, wqkv[1] + (size_t)l * 3 * DD,
                      qkv, nullptr, 0, DD, 1 << 20, 0, (long long)kBT * kD, kD, kD};
            gemm_t<128, 64, 2, 2, 0><<<dim3(16, 16, 3), 128, SM_A>>>(g);
        }
        rope_cvt<<<kBT, 512>>>(pos);
        v_cvt<<<dim3(kT / 64, kBH), 256>>>();
        g = GemmP{pq[0], pq[1], pk[0], pk[1], s, nullptr,
                  (long long)kT * kHD, (long long)kT * kHD,
                  1 << 20, 0, (long long)kT * kT, kHD, kT};
        gemm_t<128, 128, 2, 4, 2><<<dim3(8, 8, kBH), 256, SM_W>>>(g);
        softmax_cvt<<<kBH * kT, 256>>>();
        g = GemmP{pp[0], pp[1], pvt[0], pvt[1], nullptr, po,
                  (long long)kT * kT, (long long)kHD * kT,
                  kH, (long long)kT * kD, kHD, kT, kD};
        gemm_t<128, 64, 2, 2, 4><<<dim3(1, 8, kBH), 128, SM_A>>>(g);
        gh = GemmHP{po, pwo[0] + (size_t)l * DD, pwo[1] + (size_t)l * DD,
                    x, 0, 1 << 20, 0, 0, kD, kD};
        gemm_h2<128, 64, 2, 2, 1><<<dim3(16, 16, 1), 128, SM_H>>>(gh);
        // --- FFN (fp16 2-pass) ---
        rmsnorm_cvt16<<<kBT, 256>>>(x, ff_nw + (size_t)l * kD, ph);
        gh = GemmHP{ph, pw13[0] + (size_t)l * 2 * FD, pw13[1] + (size_t)l * 2 * FD,
                    f13, FD, 1 << 20, 0, (long long)kBT * kDFF, kD, kDFF};
        gemm_h2<128, 64, 2, 2, 0><<<dim3(64, 16, 2), 128, SM_H>>>(gh);
        silu_cvt16<<<kBT * kDFF / 1024, 256>>>();
        gh = GemmHP{pg, pw2[0] + (size_t)l * kD * kDFF, pw2[1] + (size_t)l * kD * kDFF,
                    x, 0, 1 << 20, 0, 0, kDFF, kD};
        gemm_h2<128, 64, 2, 2, 1><<<dim3(16, 16, 1), 128, SM_H>>>(gh);
    }

    // --- final norm + tied LM head (fp16 2-pass) ---
    rmsnorm_cvt16<<<kBT, 256>>>(x, norm_w, ph);
    gh = GemmHP{ph, pemb[0], pemb[1], out, 0, 1 << 20, 0, 0, kD, kVOCAB};
    gemm_h2<128, 64, 2, 2, 0><<<dim3(kVOCAB / 64, 16, 1), 128, SM_H>>>(gh);
}

// round 14
// speedup vs baseline: 1.3831x; 1.1158x over previous
#include <cuda_runtime.h>
#include <cuda_fp16.h>
#include <cstdint>
#include <math.h>

namespace {
constexpr int kB = 2, kT = 1024, kD = 1024, kH = 16, kHD = 64, kL = 4;
constexpr int kDFF = 4096, kVOCAB = 16384;
constexpr int kBT = kB * kT;
constexpr int kBH = kB * kH;
constexpr float kEPS = 1e-6f;
constexpr int KC = 32;     // k-chunk
constexpr int SP = 40;     // padded smem row stride (16-bit elems)
constexpr int NST = 2;     // pipeline stages
}

// ------------------------- static device scratch ---------------------------
__device__ float g_x[kBT * kD];
__device__ float g_qkv[3 * kBT * kD];
__device__ float g_s[(size_t)kBH * kT * kT];
__device__ float g_f13[2 * kBT * kDFF];
__device__ float g_inv[32];

__device__ __half h_h[kBT * kD];          // normed activations (single fp16)
__device__ __half h_o[kBT * kD];          // attention output
__device__ __half h_g[kBT * kDFF];        // silu output
__device__ __half h_q[kBH * kT * kHD];    // roped q (head-major)
__device__ __half h_k[kBH * kT * kHD];    // roped k
__device__ __half h_vt[kBH * kHD * kT];   // v transposed
__device__ __half h_p[(size_t)kBH * kT * kT];  // softmax probs
__device__ __half h_wqkv[2][kL * 3 * kD * kD];
__device__ __half h_wo[2][kL * kD * kD];
__device__ __half h_w13[2][kL * 2 * kDFF * kD];
__device__ __half h_w2[2][kL * kD * kDFF];
__device__ __half h_emb[2][kVOCAB * kD];

// ------------------------------ PTX helpers --------------------------------
__device__ __forceinline__ uint32_t smem_u32(const void* p) {
    uint32_t a;
    asm("{ .reg .u64 t; cvta.to.shared.u64 t, %1; cvt.u32.u64 %0, t; }" : "=r"(a) : "l"(p));
    return a;
}
__device__ __forceinline__ void cp16(uint32_t dst, const void* src) {
    asm volatile("cp.async.cg.shared.global [%0], [%1], 16;" :: "r"(dst), "l"(src));
}
__device__ __forceinline__ void cp_commit() { asm volatile("cp.async.commit_group;" ::: "memory"); }
__device__ __forceinline__ void cp_wait0() { asm volatile("cp.async.wait_group 0;" ::: "memory"); }

__device__ __forceinline__ void ldsm4(uint32_t& r0, uint32_t& r1, uint32_t& r2, uint32_t& r3,
                                      uint32_t addr) {
    asm volatile("ldmatrix.sync.aligned.m8n8.x4.shared.b16 {%0,%1,%2,%3},[%4];"
                 : "=r"(r0), "=r"(r1), "=r"(r2), "=r"(r3) : "r"(addr));
}
__device__ __forceinline__ void mma_f16(float* c, const uint32_t* A, const uint32_t* B) {
    asm volatile(
        "mma.sync.aligned.m16n8k16.row.col.f32.f16.f16.f32 "
        "{%0,%1,%2,%3},{%4,%5,%6,%7},{%8,%9},{%0,%1,%2,%3};"
        : "+f"(c[0]), "+f"(c[1]), "+f"(c[2]), "+f"(c[3])
        : "r"(A[0]), "r"(A[1]), "r"(A[2]), "r"(A[3]), "r"(B[0]), "r"(B[1]));
}
__device__ __forceinline__ void split_f16(float f, __half& hi, __half& lo) {
    hi = __float2half(f);
    lo = __float2half(f - __half2float(hi));
}

// ------------- batched fp32 -> (hi,lo) fp16 converter (z-indexed) ----------
struct CvtHP {
    const float* src[4];
    __half *hi[4], *lo[4];
    long long strideE[4];
    int n4, seg4;
};

__global__ void cvt_batch_h(CvtHP p) {
    const int z = blockIdx.y;
    const float4* src = reinterpret_cast<const float4*>(p.src[z]);
    __half* hi = p.hi[z];
    __half* lo = p.lo[z];
    const long long strE = p.strideE[z];
    const int stride = gridDim.x * blockDim.x;
    for (int i = blockIdx.x * blockDim.x + threadIdx.x; i < p.n4; i += stride) {
        float4 v = src[i];
        int l = i / p.seg4, r = i - l * p.seg4;
        long long d = (long long)l * strE + (long long)r * 4;
        __half h0, h1, h2, h3, l0, l1, l2, l3;
        split_f16(v.x, h0, l0); split_f16(v.y, h1, l1);
        split_f16(v.z, h2, l2); split_f16(v.w, h3, l3);
        *reinterpret_cast<__half2*>(hi + d)     = __half2(h0, h1);
        *reinterpret_cast<__half2*>(hi + d + 2) = __half2(h2, h3);
        *reinterpret_cast<__half2*>(lo + d)     = __half2(l0, l1);
        *reinterpret_cast<__half2*>(lo + d + 2) = __half2(l2, l3);
    }
}

// ------ fp16 GEMM: C[M,N] = A * B^T, NP passes over B (hi[,lo]) ------------
// A single fp16. EPI: 0 = fp32 store, 1 = fp32 add, 2 = fp32 *0.125, 3 = fp16.
struct GemmHP {
    const __half *A, *Bh, *Bl;
    float* C;
    __half* Ch;
    long long strA, strB;
    int czDiv; long long czOut, czIn;
    int K, ldC;
};

template <int BM_, int BN_, int WR, int WC, int EPI, int NP>
__global__ void __launch_bounds__(WR * WC * 32, (WR * WC * 32) <= 128 ? 3 : 2)
gemm_h(GemmHP a) {
    constexpr int NT = WR * WC * 32;
    constexpr int ST_A = 0, ST_BH = BM_ * SP, ST_BL = (BM_ + BN_) * SP;
    constexpr int SE = (BM_ + NP * BN_) * SP;
    extern __shared__ __half smh[];

    const int tid = threadIdx.x;
    const int w = tid >> 5, lane = tid & 31;
    const int wm = w / WC, wn = w % WC;
    const int K = a.K;
    const int bm = blockIdx.y * BM_, bn = blockIdx.x * BN_;
    const int z = blockIdx.z;

    const long long cOff = (long long)(z / a.czDiv) * a.czOut +
                           (long long)(z % a.czDiv) * a.czIn;
    const __half* Ag = a.A + (long long)z * a.strA + (long long)bm * K;
    const __half* Bhg = a.Bh + (long long)z * a.strB + (long long)bn * K;
    const __half* Blg = (NP == 2) ? a.Bl + (long long)z * a.strB + (long long)bn * K : nullptr;

    float acc[4][4][4];
#pragma unroll
    for (int i = 0; i < 4; i++)
#pragma unroll
        for (int j = 0; j < 4; j++)
#pragma unroll
            for (int q = 0; q < 4; q++) acc[i][j][q] = 0.f;

    auto load_chunk = [&](int st, int kt) {
        __half* s = smh + st * SE;
        const int kof = kt * KC;
#pragma unroll 2
        for (int idx = tid; idx < BM_ * 4; idx += NT) {
            int row = idx >> 2, sg = idx & 3;
            cp16(smem_u32(s + ST_A + row * SP + sg * 8),
                 Ag + (long long)row * K + kof + sg * 8);
        }
#pragma unroll 2
        for (int idx = tid; idx < BN_ * 4; idx += NT) {
            int row = idx >> 2, sg = idx & 3;
            long long go = (long long)row * K + kof + sg * 8;
            cp16(smem_u32(s + ST_BH + row * SP + sg * 8), Bhg + go);
            if (NP == 2) cp16(smem_u32(s + ST_BL + row * SP + sg * 8), Blg + go);
        }
        cp_commit();
    };

    const int a_row = wm * 64 + (lane & 15);
    const int a_kof = (lane >> 4) * 8;
    const int b_row = wn * 32 + (lane >> 4) * 8 + (lane & 7);
    const int b_kof = ((lane >> 3) & 1) * 8;

    const int nch = K / KC;
    load_chunk(0, 0);

    for (int kt = 0; kt < nch; kt++) {
        cp_wait0();
        __syncthreads();
        if (kt + 1 < nch) load_chunk((kt + 1) & 1, kt + 1);

        const __half* s = smh + (kt & 1) * SE;
#pragma unroll
        for (int k16 = 0; k16 < KC / 16; k16++) {
            const int kk = k16 * 16;
            uint32_t af[4][4], bh_[4][2], bl_[4][2];
#pragma unroll
            for (int nt = 0; nt < 2; nt++) {
                ldsm4(bh_[2 * nt][0], bh_[2 * nt][1], bh_[2 * nt + 1][0], bh_[2 * nt + 1][1],
                      smem_u32(s + ST_BH + (b_row + nt * 16) * SP + b_kof + kk));
                if (NP == 2)
                    ldsm4(bl_[2 * nt][0], bl_[2 * nt][1], bl_[2 * nt + 1][0], bl_[2 * nt + 1][1],
                          smem_u32(s + ST_BL + (b_row + nt * 16) * SP + b_kof + kk));
            }
#pragma unroll
            for (int mi = 0; mi < 4; mi++)
                ldsm4(af[mi][0], af[mi][1], af[mi][2], af[mi][3],
                      smem_u32(s + ST_A + (a_row + mi * 16) * SP + a_kof + kk));
#pragma unroll
            for (int mi = 0; mi < 4; mi++)
#pragma unroll
                for (int ni = 0; ni < 4; ni++) mma_f16(acc[mi][ni], af[mi], bh_[ni]);
            if (NP == 2) {
#pragma unroll
                for (int mi = 0; mi < 4; mi++)
#pragma unroll
                    for (int ni = 0; ni < 4; ni++) mma_f16(acc[mi][ni], af[mi], bl_[ni]);
            }
        }
    }

    const int ldC = a.ldC;
#pragma unroll
    for (int mi = 0; mi < 4; mi++) {
#pragma unroll
        for (int ni = 0; ni < 4; ni++) {
            int row0 = bm + wm * 64 + mi * 16 + (lane >> 2);
            int col = bn + wn * 32 + ni * 8 + (lane & 3) * 2;
            long long o0 = cOff + (long long)row0 * ldC + col;
            long long o1 = cOff + (long long)(row0 + 8) * ldC + col;
            if (EPI == 3) {
                *reinterpret_cast<__half2*>(a.Ch + o0) =
                    __half2(__float2half(acc[mi][ni][0]), __float2half(acc[mi][ni][1]));
                *reinterpret_cast<__half2*>(a.Ch + o1) =
                    __half2(__float2half(acc[mi][ni][2]), __float2half(acc[mi][ni][3]));
            } else {
                float sc = (EPI == 2) ? 0.125f : 1.f;
                float2 v0 = make_float2(acc[mi][ni][0] * sc, acc[mi][ni][1] * sc);
                float2 v1 = make_float2(acc[mi][ni][2] * sc, acc[mi][ni][3] * sc);
                if (EPI == 1) {
                    float2 p0 = *reinterpret_cast<const float2*>(a.C + o0);
                    float2 p1 = *reinterpret_cast<const float2*>(a.C + o1);
                    v0.x += p0.x; v0.y += p0.y; v1.x += p1.x; v1.y += p1.y;
                }
                *reinterpret_cast<float2*>(a.C + o0) = v0;
                *reinterpret_cast<float2*>(a.C + o1) = v1;
            }
        }
    }
}

// ------------------------------- elementwise -------------------------------
__global__ void embed_kernel(const int* __restrict__ tok, const float* __restrict__ emb) {
    int row = blockIdx.x;
    const float4* src = reinterpret_cast<const float4*>(emb + (size_t)tok[row] * kD);
    float4* dst = reinterpret_cast<float4*>(g_x + (size_t)row * kD);
    for (int i = threadIdx.x; i < kD / 4; i += blockDim.x) dst[i] = src[i];
}

__global__ void rmsnorm_cvt16(const float* __restrict__ in, const float* __restrict__ w,
                              __half* __restrict__ oh) {
    int row = blockIdx.x, tid = threadIdx.x;
    float4 v = reinterpret_cast<const float4*>(in + (size_t)row * kD)[tid];
    __shared__ float red[256];
    red[tid] = v.x * v.x + v.y * v.y + v.z * v.z + v.w * v.w;
    __syncthreads();
    for (int off = 128; off > 0; off >>= 1) {
        if (tid < off) red[tid] += red[tid + off];
        __syncthreads();
    }
    float inv = rsqrtf(red[0] * (1.f / kD) + kEPS);
    float4 wv = reinterpret_cast<const float4*>(w)[tid];
    size_t o = (size_t)row * kD + tid * 4;
    reinterpret_cast<__half2*>(oh + o)[0] =
        __half2(__float2half(v.x * inv * wv.x), __float2half(v.y * inv * wv.y));
    reinterpret_cast<__half2*>(oh + o)[1] =
        __half2(__float2half(v.z * inv * wv.z), __float2half(v.w * inv * wv.w));
}

__global__ void rope_init() {
    int i = threadIdx.x;
    if (i < 32) g_inv[i] = (float)(1.0 / pow(10000.0, (double)(2 * i) / (double)kHD));
}

// RoPE on q,k (from g_qkv fp32) -> single fp16 head-major [bh][t][64]
__global__ void rope_cvt(const int* __restrict__ pos) {
    int row = blockIdx.x, idx = threadIdx.x;
    int h = idx >> 5, i = idx & 31;
    int b = row >> 10, t = row & 1023;
    float ang = (float)pos[row] * g_inv[i];
    float s, c;
    sincosf(ang, &s, &c);
    const float* qs = g_qkv + (size_t)row * kD + h * kHD + 2 * i;
    const float* ks = qs + (size_t)kBT * kD;
    float qr = qs[0], qi = qs[1], kr = ks[0], ki = ks[1];
    size_t dst = ((size_t)(b * kH + h) * kT + t) * kHD + 2 * i;
    *reinterpret_cast<__half2*>(&h_q[dst]) =
        __half2(__float2half(qr * c - qi * s), __float2half(qr * s + qi * c));
    *reinterpret_cast<__half2*>(&h_k[dst]) =
        __half2(__float2half(kr * c - ki * s), __float2half(kr * s + ki * c));
}

// V transpose: g_qkv v [bt][d] -> single fp16 [bh][hd][t]
__global__ void v_cvt() {
    __shared__ float vs[64][65];
    int bh = blockIdx.y, b = bh >> 4, h = bh & 15;
    int t0 = blockIdx.x * 64;
    const float* src = g_qkv + 2LL * kBT * kD + ((size_t)(b * kT + t0)) * kD + h * kHD;
#pragma unroll
    for (int it = 0; it < 16; it++) {
        int e = it * 256 + threadIdx.x;
        int tr = e >> 6, hd = e & 63;
        vs[tr][hd] = src[(size_t)tr * kD + hd];
    }
    __syncthreads();
#pragma unroll
    for (int it = 0; it < 16; it++) {
        int e = it * 256 + threadIdx.x;
        int hd = e >> 6, tc = e & 63;
        h_vt[((size_t)bh * kHD + hd) * kT + t0 + tc] = __float2half(vs[tc][hd]);
    }
}

// softmax over rows of g_s -> single fp16 h_p
__global__ void softmax_cvt() {
    size_t row = blockIdx.x;
    const float* p = g_s + row * (size_t)kT;
    __shared__ float red[256];
    int tid = threadIdx.x;
    float v[4], m = -1e30f;
#pragma unroll
    for (int j = 0; j < 4; j++) { v[j] = p[tid + j * 256]; m = fmaxf(m, v[j]); }
    red[tid] = m;
    __syncthreads();
    for (int off = 128; off > 0; off >>= 1) {
        if (tid < off) red[tid] = fmaxf(red[tid], red[tid + off]);
        __syncthreads();
    }
    float M = red[0];
    __syncthreads();
    float sum = 0.f;
#pragma unroll
    for (int j = 0; j < 4; j++) { v[j] = expf(v[j] - M); sum += v[j]; }
    red[tid] = sum;
    __syncthreads();
    for (int off = 128; off > 0; off >>= 1) {
        if (tid < off) red[tid] += red[tid + off];
        __syncthreads();
    }
    float inv = 1.f / red[0];
#pragma unroll
    for (int j = 0; j < 4; j++)
        h_p[row * kT + tid + j * 256] = __float2half(v[j] * inv);
}

__global__ void silu_cvt16() {
    int i4 = blockIdx.x * 256 + threadIdx.x;
    float4 a = reinterpret_cast<const float4*>(g_f13)[i4];
    float4 b = reinterpret_cast<const float4*>(g_f13)[i4 + kBT * kDFF / 4];
    size_t o = (size_t)i4 * 4;
    reinterpret_cast<__half2*>(h_g + o)[0] =
        __half2(__float2half(a.x / (1.f + expf(-a.x)) * b.x),
                __float2half(a.y / (1.f + expf(-a.y)) * b.y));
    reinterpret_cast<__half2*>(h_g + o)[1] =
        __half2(__float2half(a.z / (1.f + expf(-a.z)) * b.z),
                __float2half(a.w / (1.f + expf(-a.w)) * b.w));
}

// --------------------------------- launch ----------------------------------
namespace {
constexpr int SM_H2 = (128 + 2 * 64) * SP * 2 * NST;   // 40960 B (2-pass, BN=64)
constexpr int SM_S1 = (128 + 128) * SP * 2 * NST;      // 40960 B (1-pass, BN=128)
constexpr int SM_A1 = (128 + 64) * SP * 2 * NST;       // 30720 B (1-pass, BN=64)
}

extern "C" void kernel_launch(void* const* d_in, const int* in_sizes, int n_in,
                              void* d_out, int out_size) {
    const int* tok = (const int*)d_in[0];
    const int* pos = (const int*)d_in[1];
    const float* emb = (const float*)d_in[2];
    const float* attn_nw = (const float*)d_in[3];
    const float* wq = (const float*)d_in[4];
    const float* wk = (const float*)d_in[5];
    const float* wv = (const float*)d_in[6];
    const float* wo = (const float*)d_in[7];
    const float* ff_nw = (const float*)d_in[8];
    const float* w1 = (const float*)d_in[9];
    const float* w2 = (const float*)d_in[10];
    const float* w3 = (const float*)d_in[11];
    const float* norm_w = (const float*)d_in[12];
    float* out = (float*)d_out;

    cudaFuncSetAttribute(gemm_h<128, 64, 2, 2, 0, 2>, cudaFuncAttributeMaxDynamicSharedMemorySize, SM_H2);
    cudaFuncSetAttribute(gemm_h<128, 64, 2, 2, 1, 2>, cudaFuncAttributeMaxDynamicSharedMemorySize, SM_H2);
    cudaFuncSetAttribute(gemm_h<128, 128, 2, 4, 2, 1>, cudaFuncAttributeMaxDynamicSharedMemorySize, SM_S1);
    cudaFuncSetAttribute(gemm_h<128, 64, 2, 2, 3, 1>, cudaFuncAttributeMaxDynamicSharedMemorySize, SM_A1);

    float *x, *qkv, *s, *f13;
    cudaGetSymbolAddress((void**)&x, g_x);
    cudaGetSymbolAddress((void**)&qkv, g_qkv);
    cudaGetSymbolAddress((void**)&s, g_s);
    cudaGetSymbolAddress((void**)&f13, g_f13);

    __half *ph, *po, *pg, *pq, *pk, *pvt, *pp;
    cudaGetSymbolAddress((void**)&ph, h_h);
    cudaGetSymbolAddress((void**)&po, h_o);
    cudaGetSymbolAddress((void**)&pg, h_g);
    cudaGetSymbolAddress((void**)&pq, h_q);
    cudaGetSymbolAddress((void**)&pk, h_k);
    cudaGetSymbolAddress((void**)&pvt, h_vt);
    cudaGetSymbolAddress((void**)&pp, h_p);
    __half *pwqkv[2], *pwo[2], *pw13[2], *pw2[2], *pemb[2];
    for (int si = 0; si < 2; si++) {
        cudaGetSymbolAddress((void**)&pwqkv[si], h_wqkv);
        cudaGetSymbolAddress((void**)&pwo[si], h_wo);
        cudaGetSymbolAddress((void**)&pw13[si], h_w13);
        cudaGetSymbolAddress((void**)&pw2[si], h_w2);
        cudaGetSymbolAddress((void**)&pemb[si], h_emb);
        pwqkv[si] += (size_t)si * kL * 3 * kD * kD;
        pwo[si] += (size_t)si * kL * kD * kD;
        pw13[si] += (size_t)si * kL * 2 * kDFF * kD;
        pw2[si] += (size_t)si * kL * kD * kDFF;
        pemb[si] += (size_t)si * kVOCAB * kD;
    }

    const int DD = kD * kD, FD = kDFF * kD;

    // 0: wq,wk,wv interleave into h_wqkv; wo contiguous
    {
        CvtHP p{};
        p.src[0] = wq; p.src[1] = wk; p.src[2] = wv; p.src[3] = wo;
        p.hi[0] = pwqkv[0]; p.hi[1] = pwqkv[0] + DD; p.hi[2] = pwqkv[0] + 2 * DD; p.hi[3] = pwo[0];
        p.lo[0] = pwqkv[1]; p.lo[1] = pwqkv[1] + DD; p.lo[2] = pwqkv[1] + 2 * DD; p.lo[3] = pwo[1];
        p.strideE[0] = p.strideE[1] = p.strideE[2] = 3LL * DD;
        p.strideE[3] = DD;
        p.n4 = kL * DD / 4; p.seg4 = DD / 4;
        cvt_batch_h<<<dim3(1024, 4), 256>>>(p);
    }
    embed_kernel<<<kBT, 256>>>(tok, emb);                   // 1
    rmsnorm_cvt16<<<kBT, 256>>>(x, attn_nw, ph);            // 2

    GemmHP g{};
    g = GemmHP{ph, pwqkv[0], pwqkv[1], qkv, nullptr,
               0, DD, 1 << 20, 0, (long long)kBT * kD, kD, kD};
    gemm_h<128, 64, 2, 2, 0, 2><<<dim3(16, 16, 3), 128, SM_H2>>>(g);  // 3: ncu target

    {   // 4: w1,w3 interleave; w2, emb contiguous
        CvtHP p{};
        p.src[0] = w1; p.src[1] = w3; p.src[2] = w2; p.src[3] = emb;
        p.hi[0] = pw13[0]; p.hi[1] = pw13[0] + FD; p.hi[2] = pw2[0]; p.hi[3] = pemb[0];
        p.lo[0] = pw13[1]; p.lo[1] = pw13[1] + FD; p.lo[2] = pw2[1]; p.lo[3] = pemb[1];
        p.strideE[0] = p.strideE[1] = 2LL * FD;
        p.strideE[2] = FD; p.strideE[3] = FD;
        p.n4 = kL * FD / 4; p.seg4 = FD / 4;
        cvt_batch_h<<<dim3(2048, 4), 256>>>(p);
    }
    rope_init<<<1, 32>>>();                                 // 5

    for (int l = 0; l < kL; l++) {
        if (l > 0) {
            rmsnorm_cvt16<<<kBT, 256>>>(x, attn_nw + (size_t)l * kD, ph);
            g = GemmHP{ph, pwqkv[0] + (size_t)l * 3 * DD, pwqkv[1] + (size_t)l * 3 * DD,
                       qkv, nullptr, 0, DD, 1 << 20, 0, (long long)kBT * kD, kD, kD};
            gemm_h<128, 64, 2, 2, 0, 2><<<dim3(16, 16, 3), 128, SM_H2>>>(g);
        }
        rope_cvt<<<kBT, 512>>>(pos);
        v_cvt<<<dim3(kT / 64, kBH), 256>>>();
        // scores: q*k^T (both single fp16, 1 pass)
        g = GemmHP{pq, pk, nullptr, s, nullptr,
                   (long long)kT * kHD, (long long)kT * kHD,
                   1 << 20, 0, (long long)kT * kT, kHD, kT};
        gemm_h<128, 128, 2, 4, 2, 1><<<dim3(8, 8, kBH), 256, SM_S1>>>(g);
        softmax_cvt<<<kBH * kT, 256>>>();
        // av: P*V^T (both single fp16, 1 pass) -> fp16 h_o (head interleave)
        g = GemmHP{pp, pvt, nullptr, nullptr, po,
                   (long long)kT * kT, (long long)kHD * kT,
                   kH, (long long)kT * kD, kHD, kT, kD};
        gemm_h<128, 64, 2, 2, 3, 1><<<dim3(1, 8, kBH), 128, SM_A1>>>(g);
        // wo (fp16 2-pass, accumulate into x)
        g = GemmHP{po, pwo[0] + (size_t)l * DD, pwo[1] + (size_t)l * DD,
                   x, nullptr, 0, 0, 1 << 20, 0, 0, kD, kD};
        gemm_h<128, 64, 2, 2, 1, 2><<<dim3(16, 16, 1), 128, SM_H2>>>(g);
        // --- FFN ---
        rmsnorm_cvt16<<<kBT, 256>>>(x, ff_nw + (size_t)l * kD, ph);
        g = GemmHP{ph, pw13[0] + (size_t)l * 2 * FD, pw13[1] + (size_t)l * 2 * FD,
                   f13, nullptr, 0, FD, 1 << 20, 0, (long long)kBT * kDFF, kD, kDFF};
        gemm_h<128, 64, 2, 2, 0, 2><<<dim3(64, 16, 2), 128, SM_H2>>>(g);
        silu_cvt16<<<kBT * kDFF / 1024, 256>>>();
        g = GemmHP{pg, pw2[0] + (size_t)l * kD * kDFF, pw2[1] + (size_t)l * kD * kDFF,
                   x, nullptr, 0, 0, 1 << 20, 0, 0, kDFF, kD};
        gemm_h<128, 64, 2, 2, 1, 2><<<dim3(16, 16, 1), 128, SM_H2>>>(g);
    }

    // --- final norm + tied LM head ---
    rmsnorm_cvt16<<<kBT, 256>>>(x, norm_w, ph);
    g = GemmHP{ph, pemb[0], pemb[1], out, nullptr,
               0, 0, 1 << 20, 0, 0, kD, kVOCAB};
    gemm_h<128, 64, 2, 2, 0, 2><<<dim3(kVOCAB / 64, 16, 1), 128, SM_H2>>>(g);
}

// round 15
// speedup vs baseline: 1.4464x; 1.0458x over previous
#include <cuda_runtime.h>
#include <cuda_fp16.h>
#include <cstdint>
#include <math.h>

namespace {
constexpr int kB = 2, kT = 1024, kD = 1024, kH = 16, kHD = 64, kL = 4;
constexpr int kDFF = 4096, kVOCAB = 16384;
constexpr int kBT = kB * kT;
constexpr int kBH = kB * kH;
constexpr float kEPS = 1e-6f;
constexpr int KC = 32;     // k-chunk
constexpr int SP = 40;     // padded smem row stride (16-bit elems)
constexpr int NST = 2;     // pipeline stages
}

// ------------------------- static device scratch ---------------------------
__device__ float g_x[kBT * kD];
__device__ float g_qkv[3 * kBT * kD];
__device__ float g_s[(size_t)kBH * kT * kT];
__device__ float g_f13[2 * kBT * kDFF];
__device__ float g_part[4 * kBT * kD];    // split-K partial sums
__device__ float g_inv[32];

__device__ __half h_h[kBT * kD];
__device__ __half h_o[kBT * kD];
__device__ __half h_g[kBT * kDFF];
__device__ __half h_q[kBH * kT * kHD];
__device__ __half h_k[kBH * kT * kHD];
__device__ __half h_vt[kBH * kHD * kT];
__device__ __half h_p[(size_t)kBH * kT * kT];
__device__ __half h_wqkv[2][kL * 3 * kD * kD];
__device__ __half h_wo[2][kL * kD * kD];
__device__ __half h_w13[2][kL * 2 * kDFF * kD];
__device__ __half h_w2[2][kL * kD * kDFF];
__device__ __half h_emb[2][kVOCAB * kD];

// ------------------------------ PTX helpers --------------------------------
__device__ __forceinline__ uint32_t smem_u32(const void* p) {
    uint32_t a;
    asm("{ .reg .u64 t; cvta.to.shared.u64 t, %1; cvt.u32.u64 %0, t; }" : "=r"(a) : "l"(p));
    return a;
}
__device__ __forceinline__ void cp16(uint32_t dst, const void* src) {
    asm volatile("cp.async.cg.shared.global [%0], [%1], 16;" :: "r"(dst), "l"(src));
}
__device__ __forceinline__ void cp_commit() { asm volatile("cp.async.commit_group;" ::: "memory"); }
__device__ __forceinline__ void cp_wait0() { asm volatile("cp.async.wait_group 0;" ::: "memory"); }

__device__ __forceinline__ void ldsm4(uint32_t& r0, uint32_t& r1, uint32_t& r2, uint32_t& r3,
                                      uint32_t addr) {
    asm volatile("ldmatrix.sync.aligned.m8n8.x4.shared.b16 {%0,%1,%2,%3},[%4];"
                 : "=r"(r0), "=r"(r1), "=r"(r2), "=r"(r3) : "r"(addr));
}
__device__ __forceinline__ void mma_f16(float* c, const uint32_t* A, const uint32_t* B) {
    asm volatile(
        "mma.sync.aligned.m16n8k16.row.col.f32.f16.f16.f32 "
        "{%0,%1,%2,%3},{%4,%5,%6,%7},{%8,%9},{%0,%1,%2,%3};"
        : "+f"(c[0]), "+f"(c[1]), "+f"(c[2]), "+f"(c[3])
        : "r"(A[0]), "r"(A[1]), "r"(A[2]), "r"(A[3]), "r"(B[0]), "r"(B[1]));
}
__device__ __forceinline__ void split_f16(float f, __half& hi, __half& lo) {
    hi = __float2half(f);
    lo = __float2half(f - __half2float(hi));
}

// ------------- batched fp32 -> (hi,lo) fp16 converter (z-indexed) ----------
struct CvtHP {
    const float* src[4];
    __half *hi[4], *lo[4];
    long long strideE[4];
    int n4, seg4;
};

__global__ void cvt_batch_h(CvtHP p) {
    const int z = blockIdx.y;
    const float4* src = reinterpret_cast<const float4*>(p.src[z]);
    __half* hi = p.hi[z];
    __half* lo = p.lo[z];
    const long long strE = p.strideE[z];
    const int stride = gridDim.x * blockDim.x;
    for (int i = blockIdx.x * blockDim.x + threadIdx.x; i < p.n4; i += stride) {
        float4 v = src[i];
        int l = i / p.seg4, r = i - l * p.seg4;
        long long d = (long long)l * strE + (long long)r * 4;
        __half h0, h1, h2, h3, l0, l1, l2, l3;
        split_f16(v.x, h0, l0); split_f16(v.y, h1, l1);
        split_f16(v.z, h2, l2); split_f16(v.w, h3, l3);
        *reinterpret_cast<__half2*>(hi + d)     = __half2(h0, h1);
        *reinterpret_cast<__half2*>(hi + d + 2) = __half2(h2, h3);
        *reinterpret_cast<__half2*>(lo + d)     = __half2(l0, l1);
        *reinterpret_cast<__half2*>(lo + d + 2) = __half2(l2, l3);
    }
}

// ------ fp16 GEMM: C[M,N] = A * B^T, NP passes over B (hi[,lo]) ------------
// A single fp16. Kst = row stride; per-z base offsets (strA/strB) allow both
// batching and split-K. EPI: 0 = fp32 store, 2 = fp32 *0.125, 3 = fp16 store.
struct GemmHP {
    const __half *A, *Bh, *Bl;
    float* C;
    __half* Ch;
    long long strA, strB;
    int czDiv; long long czOut, czIn;
    int K, Kst, ldC;
};

template <int BM_, int BN_, int WR, int WC, int EPI, int NP>
__global__ void __launch_bounds__(WR * WC * 32, (WR * WC * 32) <= 128 ? 3 : 2)
gemm_h(GemmHP a) {
    constexpr int NT = WR * WC * 32;
    constexpr int ST_A = 0, ST_BH = BM_ * SP, ST_BL = (BM_ + BN_) * SP;
    constexpr int SE = (BM_ + NP * BN_) * SP;
    extern __shared__ __half smh[];

    const int tid = threadIdx.x;
    const int w = tid >> 5, lane = tid & 31;
    const int wm = w / WC, wn = w % WC;
    const int K = a.K, Kst = a.Kst;
    const int bm = blockIdx.y * BM_, bn = blockIdx.x * BN_;
    const int z = blockIdx.z;

    const long long cOff = (long long)(z / a.czDiv) * a.czOut +
                           (long long)(z % a.czDiv) * a.czIn;
    const __half* Ag = a.A + (long long)z * a.strA + (long long)bm * Kst;
    const __half* Bhg = a.Bh + (long long)z * a.strB + (long long)bn * Kst;
    const __half* Blg = (NP == 2) ? a.Bl + (long long)z * a.strB + (long long)bn * Kst : nullptr;

    float acc[4][4][4];
#pragma unroll
    for (int i = 0; i < 4; i++)
#pragma unroll
        for (int j = 0; j < 4; j++)
#pragma unroll
            for (int q = 0; q < 4; q++) acc[i][j][q] = 0.f;

    auto load_chunk = [&](int st, int kt) {
        __half* s = smh + st * SE;
        const int kof = kt * KC;
#pragma unroll 2
        for (int idx = tid; idx < BM_ * 4; idx += NT) {
            int row = idx >> 2, sg = idx & 3;
            cp16(smem_u32(s + ST_A + row * SP + sg * 8),
                 Ag + (long long)row * Kst + kof + sg * 8);
        }
#pragma unroll 2
        for (int idx = tid; idx < BN_ * 4; idx += NT) {
            int row = idx >> 2, sg = idx & 3;
            long long go = (long long)row * Kst + kof + sg * 8;
            cp16(smem_u32(s + ST_BH + row * SP + sg * 8), Bhg + go);
            if (NP == 2) cp16(smem_u32(s + ST_BL + row * SP + sg * 8), Blg + go);
        }
        cp_commit();
    };

    const int a_row = wm * 64 + (lane & 15);
    const int a_kof = (lane >> 4) * 8;
    const int b_row = wn * 32 + (lane >> 4) * 8 + (lane & 7);
    const int b_kof = ((lane >> 3) & 1) * 8;

    const int nch = K / KC;
    load_chunk(0, 0);

    for (int kt = 0; kt < nch; kt++) {
        cp_wait0();
        __syncthreads();
        if (kt + 1 < nch) load_chunk((kt + 1) & 1, kt + 1);

        const __half* s = smh + (kt & 1) * SE;
#pragma unroll
        for (int k16 = 0; k16 < KC / 16; k16++) {
            const int kk = k16 * 16;
            uint32_t af[4][4], bh_[4][2], bl_[4][2];
#pragma unroll
            for (int nt = 0; nt < 2; nt++) {
                ldsm4(bh_[2 * nt][0], bh_[2 * nt][1], bh_[2 * nt + 1][0], bh_[2 * nt + 1][1],
                      smem_u32(s + ST_BH + (b_row + nt * 16) * SP + b_kof + kk));
                if (NP == 2)
                    ldsm4(bl_[2 * nt][0], bl_[2 * nt][1], bl_[2 * nt + 1][0], bl_[2 * nt + 1][1],
                          smem_u32(s + ST_BL + (b_row + nt * 16) * SP + b_kof + kk));
            }
#pragma unroll
            for (int mi = 0; mi < 4; mi++)
                ldsm4(af[mi][0], af[mi][1], af[mi][2], af[mi][3],
                      smem_u32(s + ST_A + (a_row + mi * 16) * SP + a_kof + kk));
#pragma unroll
            for (int mi = 0; mi < 4; mi++)
#pragma unroll
                for (int ni = 0; ni < 4; ni++) mma_f16(acc[mi][ni], af[mi], bh_[ni]);
            if (NP == 2) {
#pragma unroll
                for (int mi = 0; mi < 4; mi++)
#pragma unroll
                    for (int ni = 0; ni < 4; ni++) mma_f16(acc[mi][ni], af[mi], bl_[ni]);
            }
        }
    }

    const int ldC = a.ldC;
#pragma unroll
    for (int mi = 0; mi < 4; mi++) {
#pragma unroll
        for (int ni = 0; ni < 4; ni++) {
            int row0 = bm + wm * 64 + mi * 16 + (lane >> 2);
            int col = bn + wn * 32 + ni * 8 + (lane & 3) * 2;
            long long o0 = cOff + (long long)row0 * ldC + col;
            long long o1 = cOff + (long long)(row0 + 8) * ldC + col;
            if (EPI == 3) {
                *reinterpret_cast<__half2*>(a.Ch + o0) =
                    __half2(__float2half(acc[mi][ni][0]), __float2half(acc[mi][ni][1]));
                *reinterpret_cast<__half2*>(a.Ch + o1) =
                    __half2(__float2half(acc[mi][ni][2]), __float2half(acc[mi][ni][3]));
            } else {
                float sc = (EPI == 2) ? 0.125f : 1.f;
                *reinterpret_cast<float2*>(a.C + o0) =
                    make_float2(acc[mi][ni][0] * sc, acc[mi][ni][1] * sc);
                *reinterpret_cast<float2*>(a.C + o1) =
                    make_float2(acc[mi][ni][2] * sc, acc[mi][ni][3] * sc);
            }
        }
    }
}

// ------------------------------- elementwise -------------------------------
__global__ void embed_kernel(const int* __restrict__ tok, const float* __restrict__ emb) {
    int row = blockIdx.x;
    const float4* src = reinterpret_cast<const float4*>(emb + (size_t)tok[row] * kD);
    float4* dst = reinterpret_cast<float4*>(g_x + (size_t)row * kD);
    for (int i = threadIdx.x; i < kD / 4; i += blockDim.x) dst[i] = src[i];
}

__global__ void rmsnorm_cvt16(const float* __restrict__ in, const float* __restrict__ w,
                              __half* __restrict__ oh) {
    int row = blockIdx.x, tid = threadIdx.x;
    float4 v = reinterpret_cast<const float4*>(in + (size_t)row * kD)[tid];
    __shared__ float red[256];
    red[tid] = v.x * v.x + v.y * v.y + v.z * v.z + v.w * v.w;
    __syncthreads();
    for (int off = 128; off > 0; off >>= 1) {
        if (tid < off) red[tid] += red[tid + off];
        __syncthreads();
    }
    float inv = rsqrtf(red[0] * (1.f / kD) + kEPS);
    float4 wv = reinterpret_cast<const float4*>(w)[tid];
    size_t o = (size_t)row * kD + tid * 4;
    reinterpret_cast<__half2*>(oh + o)[0] =
        __half2(__float2half(v.x * inv * wv.x), __float2half(v.y * inv * wv.y));
    reinterpret_cast<__half2*>(oh + o)[1] =
        __half2(__float2half(v.z * inv * wv.z), __float2half(v.w * inv * wv.w));
}

// x += sum of 4 split-K partials; write x; then rmsnorm -> fp16
__global__ void rmsnorm_add_cvt16(float* __restrict__ x, const float* __restrict__ part,
                                  const float* __restrict__ w, __half* __restrict__ oh) {
    int row = blockIdx.x, tid = threadIdx.x;
    size_t o4 = (size_t)row * (kD / 4) + tid;
    float4 v = reinterpret_cast<float4*>(x)[o4];
#pragma unroll
    for (int s = 0; s < 4; s++) {
        float4 p = reinterpret_cast<const float4*>(part + (size_t)s * kBT * kD)[o4];
        v.x += p.x; v.y += p.y; v.z += p.z; v.w += p.w;
    }
    reinterpret_cast<float4*>(x)[o4] = v;
    __shared__ float red[256];
    red[tid] = v.x * v.x + v.y * v.y + v.z * v.z + v.w * v.w;
    __syncthreads();
    for (int off = 128; off > 0; off >>= 1) {
        if (tid < off) red[tid] += red[tid + off];
        __syncthreads();
    }
    float inv = rsqrtf(red[0] * (1.f / kD) + kEPS);
    float4 wv = reinterpret_cast<const float4*>(w)[tid];
    size_t o = (size_t)row * kD + tid * 4;
    reinterpret_cast<__half2*>(oh + o)[0] =
        __half2(__float2half(v.x * inv * wv.x), __float2half(v.y * inv * wv.y));
    reinterpret_cast<__half2*>(oh + o)[1] =
        __half2(__float2half(v.z * inv * wv.z), __float2half(v.w * inv * wv.w));
}

__global__ void rope_init() {
    int i = threadIdx.x;
    if (i < 32) g_inv[i] = (float)(1.0 / pow(10000.0, (double)(2 * i) / (double)kHD));
}

__global__ void rope_cvt(const int* __restrict__ pos) {
    int row = blockIdx.x, idx = threadIdx.x;
    int h = idx >> 5, i = idx & 31;
    int b = row >> 10, t = row & 1023;
    float ang = (float)pos[row] * g_inv[i];
    float s, c;
    sincosf(ang, &s, &c);
    const float* qs = g_qkv + (size_t)row * kD + h * kHD + 2 * i;
    const float* ks = qs + (size_t)kBT * kD;
    float qr = qs[0], qi = qs[1], kr = ks[0], ki = ks[1];
    size_t dst = ((size_t)(b * kH + h) * kT + t) * kHD + 2 * i;
    *reinterpret_cast<__half2*>(&h_q[dst]) =
        __half2(__float2half(qr * c - qi * s), __float2half(qr * s + qi * c));
    *reinterpret_cast<__half2*>(&h_k[dst]) =
        __half2(__float2half(kr * c - ki * s), __float2half(kr * s + ki * c));
}

__global__ void v_cvt() {
    __shared__ float vs[64][65];
    int bh = blockIdx.y, b = bh >> 4, h = bh & 15;
    int t0 = blockIdx.x * 64;
    const float* src = g_qkv + 2LL * kBT * kD + ((size_t)(b * kT + t0)) * kD + h * kHD;
#pragma unroll
    for (int it = 0; it < 16; it++) {
        int e = it * 256 + threadIdx.x;
        int tr = e >> 6, hd = e & 63;
        vs[tr][hd] = src[(size_t)tr * kD + hd];
    }
    __syncthreads();
#pragma unroll
    for (int it = 0; it < 16; it++) {
        int e = it * 256 + threadIdx.x;
        int hd = e >> 6, tc = e & 63;
        h_vt[((size_t)bh * kHD + hd) * kT + t0 + tc] = __float2half(vs[tc][hd]);
    }
}

__global__ void softmax_cvt() {
    size_t row = blockIdx.x;
    const float* p = g_s + row * (size_t)kT;
    __shared__ float red[256];
    int tid = threadIdx.x;
    float v[4], m = -1e30f;
#pragma unroll
    for (int j = 0; j < 4; j++) { v[j] = p[tid + j * 256]; m = fmaxf(m, v[j]); }
    red[tid] = m;
    __syncthreads();
    for (int off = 128; off > 0; off >>= 1) {
        if (tid < off) red[tid] = fmaxf(red[tid], red[tid + off]);
        __syncthreads();
    }
    float M = red[0];
    __syncthreads();
    float sum = 0.f;
#pragma unroll
    for (int j = 0; j < 4; j++) { v[j] = expf(v[j] - M); sum += v[j]; }
    red[tid] = sum;
    __syncthreads();
    for (int off = 128; off > 0; off >>= 1) {
        if (tid < off) red[tid] += red[tid + off];
        __syncthreads();
    }
    float inv = 1.f / red[0];
#pragma unroll
    for (int j = 0; j < 4; j++)
        h_p[row * kT + tid + j * 256] = __float2half(v[j] * inv);
}

__global__ void silu_cvt16() {
    int i4 = blockIdx.x * 256 + threadIdx.x;
    float4 a = reinterpret_cast<const float4*>(g_f13)[i4];
    float4 b = reinterpret_cast<const float4*>(g_f13)[i4 + kBT * kDFF / 4];
    size_t o = (size_t)i4 * 4;
    reinterpret_cast<__half2*>(h_g + o)[0] =
        __half2(__float2half(a.x / (1.f + expf(-a.x)) * b.x),
                __float2half(a.y / (1.f + expf(-a.y)) * b.y));
    reinterpret_cast<__half2*>(h_g + o)[1] =
        __half2(__float2half(a.z / (1.f + expf(-a.z)) * b.z),
                __float2half(a.w / (1.f + expf(-a.w)) * b.w));
}

// --------------------------------- launch ----------------------------------
namespace {
constexpr int SM_H2 = (128 + 2 * 64) * SP * 2 * NST;   // 40960 B (2-pass, BN=64)
constexpr int SM_S1 = (128 + 128) * SP * 2 * NST;      // 40960 B (1-pass, BN=128)
constexpr int SM_A1 = (128 + 64) * SP * 2 * NST;       // 30720 B (1-pass, BN=64)
}

extern "C" void kernel_launch(void* const* d_in, const int* in_sizes, int n_in,
                              void* d_out, int out_size) {
    const int* tok = (const int*)d_in[0];
    const int* pos = (const int*)d_in[1];
    const float* emb = (const float*)d_in[2];
    const float* attn_nw = (const float*)d_in[3];
    const float* wq = (const float*)d_in[4];
    const float* wk = (const float*)d_in[5];
    const float* wv = (const float*)d_in[6];
    const float* wo = (const float*)d_in[7];
    const float* ff_nw = (const float*)d_in[8];
    const float* w1 = (const float*)d_in[9];
    const float* w2 = (const float*)d_in[10];
    const float* w3 = (const float*)d_in[11];
    const float* norm_w = (const float*)d_in[12];
    float* out = (float*)d_out;

    cudaFuncSetAttribute(gemm_h<128, 64, 2, 2, 0, 2>, cudaFuncAttributeMaxDynamicSharedMemorySize, SM_H2);
    cudaFuncSetAttribute(gemm_h<128, 128, 2, 4, 2, 1>, cudaFuncAttributeMaxDynamicSharedMemorySize, SM_S1);
    cudaFuncSetAttribute(gemm_h<128, 64, 2, 2, 3, 1>, cudaFuncAttributeMaxDynamicSharedMemorySize, SM_A1);

    float *x, *qkv, *s, *f13, *part;
    cudaGetSymbolAddress((void**)&x, g_x);
    cudaGetSymbolAddress((void**)&qkv, g_qkv);
    cudaGetSymbolAddress((void**)&s, g_s);
    cudaGetSymbolAddress((void**)&f13, g_f13);
    cudaGetSymbolAddress((void**)&part, g_part);

    __half *ph, *po, *pg, *pq, *pk, *pvt, *pp;
    cudaGetSymbolAddress((void**)&ph, h_h);
    cudaGetSymbolAddress((void**)&po, h_o);
    cudaGetSymbolAddress((void**)&pg, h_g);
    cudaGetSymbolAddress((void**)&pq, h_q);
    cudaGetSymbolAddress((void**)&pk, h_k);
    cudaGetSymbolAddress((void**)&pvt, h_vt);
    cudaGetSymbolAddress((void**)&pp, h_p);
    __half *pwqkv[2], *pwo[2], *pw13[2], *pw2[2], *pemb[2];
    for (int si = 0; si < 2; si++) {
        cudaGetSymbolAddress((void**)&pwqkv[si], h_wqkv);
        cudaGetSymbolAddress((void**)&pwo[si], h_wo);
        cudaGetSymbolAddress((void**)&pw13[si], h_w13);
        cudaGetSymbolAddress((void**)&pw2[si], h_w2);
        cudaGetSymbolAddress((void**)&pemb[si], h_emb);
        pwqkv[si] += (size_t)si * kL * 3 * kD * kD;
        pwo[si] += (size_t)si * kL * kD * kD;
        pw13[si] += (size_t)si * kL * 2 * kDFF * kD;
        pw2[si] += (size_t)si * kL * kD * kDFF;
        pemb[si] += (size_t)si * kVOCAB * kD;
    }

    const int DD = kD * kD, FD = kDFF * kD;
    const long long PB = (long long)kBT * kD;   // partial-buffer stride

    // 0: wq,wk,wv interleave into h_wqkv; wo contiguous
    {
        CvtHP p{};
        p.src[0] = wq; p.src[1] = wk; p.src[2] = wv; p.src[3] = wo;
        p.hi[0] = pwqkv[0]; p.hi[1] = pwqkv[0] + DD; p.hi[2] = pwqkv[0] + 2 * DD; p.hi[3] = pwo[0];
        p.lo[0] = pwqkv[1]; p.lo[1] = pwqkv[1] + DD; p.lo[2] = pwqkv[1] + 2 * DD; p.lo[3] = pwo[1];
        p.strideE[0] = p.strideE[1] = p.strideE[2] = 3LL * DD;
        p.strideE[3] = DD;
        p.n4 = kL * DD / 4; p.seg4 = DD / 4;
        cvt_batch_h<<<dim3(1024, 4), 256>>>(p);
    }
    embed_kernel<<<kBT, 256>>>(tok, emb);                   // 1
    rmsnorm_cvt16<<<kBT, 256>>>(x, attn_nw, ph);            // 2

    GemmHP g{};
    g = GemmHP{ph, pwqkv[0], pwqkv[1], qkv, nullptr,
               0, DD, 1 << 20, 0, PB, kD, kD, kD};
    gemm_h<128, 64, 2, 2, 0, 2><<<dim3(16, 16, 3), 128, SM_H2>>>(g);  // 3: ncu target

    {   // 4: w1,w3 interleave; w2, emb contiguous
        CvtHP p{};
        p.src[0] = w1; p.src[1] = w3; p.src[2] = w2; p.src[3] = emb;
        p.hi[0] = pw13[0]; p.hi[1] = pw13[0] + FD; p.hi[2] = pw2[0]; p.hi[3] = pemb[0];
        p.lo[0] = pw13[1]; p.lo[1] = pw13[1] + FD; p.lo[2] = pw2[1]; p.lo[3] = pemb[1];
        p.strideE[0] = p.strideE[1] = 2LL * FD;
        p.strideE[2] = FD; p.strideE[3] = FD;
        p.n4 = kL * FD / 4; p.seg4 = FD / 4;
        cvt_batch_h<<<dim3(2048, 4), 256>>>(p);
    }
    rope_init<<<1, 32>>>();                                 // 5

    for (int l = 0; l < kL; l++) {
        if (l > 0) {
            // x += w2 partials (prev layer), then attn norm
            rmsnorm_add_cvt16<<<kBT, 256>>>(x, part, attn_nw + (size_t)l * kD, ph);
            g = GemmHP{ph, pwqkv[0] + (size_t)l * 3 * DD, pwqkv[1] + (size_t)l * 3 * DD,
                       qkv, nullptr, 0, DD, 1 << 20, 0, PB, kD, kD, kD};
            gemm_h<128, 64, 2, 2, 0, 2><<<dim3(16, 16, 3), 128, SM_H2>>>(g);
        }
        rope_cvt<<<kBT, 512>>>(pos);
        v_cvt<<<dim3(kT / 64, kBH), 256>>>();
        // scores: q*k^T (fp16 1-pass)
        g = GemmHP{pq, pk, nullptr, s, nullptr,
                   (long long)kT * kHD, (long long)kT * kHD,
                   1 << 20, 0, (long long)kT * kT, kHD, kHD, kT};
        gemm_h<128, 128, 2, 4, 2, 1><<<dim3(8, 8, kBH), 256, SM_S1>>>(g);
        softmax_cvt<<<kBH * kT, 256>>>();
        // av: P*V^T (fp16 1-pass) -> fp16 h_o
        g = GemmHP{pp, pvt, nullptr, nullptr, po,
                   (long long)kT * kT, (long long)kHD * kT,
                   kH, (long long)kT * kD, kHD, kT, kT, kD};
        gemm_h<128, 64, 2, 2, 3, 1><<<dim3(1, 8, kBH), 128, SM_A1>>>(g);
        // wo: split-K x4 into partials (K=256 each)
        g = GemmHP{po, pwo[0] + (size_t)l * DD, pwo[1] + (size_t)l * DD,
                   part, nullptr, 256, 256, 1, PB, 0, 256, kD, kD};
        gemm_h<128, 64, 2, 2, 0, 2><<<dim3(16, 16, 4), 128, SM_H2>>>(g);
        // --- FFN ---
        // x += wo partials, then ffn norm
        rmsnorm_add_cvt16<<<kBT, 256>>>(x, part, ff_nw + (size_t)l * kD, ph);
        g = GemmHP{ph, pw13[0] + (size_t)l * 2 * FD, pw13[1] + (size_t)l * 2 * FD,
                   f13, nullptr, 0, FD, 1 << 20, 0, (long long)kBT * kDFF, kD, kD, kDFF};
        gemm_h<128, 64, 2, 2, 0, 2><<<dim3(64, 16, 2), 128, SM_H2>>>(g);
        silu_cvt16<<<kBT * kDFF / 1024, 256>>>();
        // w2: split-K x4 into partials (K=1024 each, Kst=4096)
        g = GemmHP{pg, pw2[0] + (size_t)l * kD * kDFF, pw2[1] + (size_t)l * kD * kDFF,
                   part, nullptr, 1024, 1024, 1, PB, 0, 1024, kDFF, kD};
        gemm_h<128, 64, 2, 2, 0, 2><<<dim3(16, 16, 4), 128, SM_H2>>>(g);
    }

    // --- final: x += w2 partials, norm, tied LM head ---
    rmsnorm_add_cvt16<<<kBT, 256>>>(x, part, norm_w, ph);
    GemmHP g2{ph, pemb[0], pemb[1], out, nullptr,
              0, 0, 1 << 20, 0, 0, kD, kD, kVOCAB};
    gemm_h<128, 64, 2, 2, 0, 2><<<dim3(kVOCAB / 64, 16, 1), 128, SM_H2>>>(g2);
}

// round 16
// speedup vs baseline: 1.4675x; 1.0146x over previous
#include <cuda_runtime.h>
#include <cuda_fp16.h>
#include <cstdint>
#include <math.h>

namespace {
constexpr int kB = 2, kT = 1024, kD = 1024, kH = 16, kHD = 64, kL = 4;
constexpr int kDFF = 4096, kVOCAB = 16384;
constexpr int kBT = kB * kT;
constexpr int kBH = kB * kH;
constexpr float kEPS = 1e-6f;
constexpr int KC = 32;     // k-chunk
constexpr int SP = 40;     // padded smem row stride (16-bit elems)
constexpr int NST = 2;     // pipeline stages
}

// ------------------------- static device scratch ---------------------------
__device__ float g_x[kBT * kD];
__device__ float g_qkv[3 * kBT * kD];
__device__ float g_f13[2 * kBT * kDFF];
__device__ float g_part[4 * kBT * kD];    // split-K partial sums
__device__ float g_inv[32];

__device__ __half h_h[kBT * kD];
__device__ __half h_o[kBT * kD];
__device__ __half h_g[kBT * kDFF];
__device__ __half h_q[kBH * kT * kHD];
__device__ __half h_k[kBH * kT * kHD];
__device__ __half h_vt[kBH * kHD * kT];
__device__ __half h_p[(size_t)kBH * kT * kT];  // scores -> probs (in place)
__device__ __half h_wqkv[2][kL * 3 * kD * kD];
__device__ __half h_wo[2][kL * kD * kD];
__device__ __half h_w13[2][kL * 2 * kDFF * kD];
__device__ __half h_w2[2][kL * kD * kDFF];
__device__ __half h_emb[2][kVOCAB * kD];

// ------------------------------ PTX helpers --------------------------------
__device__ __forceinline__ uint32_t smem_u32(const void* p) {
    uint32_t a;
    asm("{ .reg .u64 t; cvta.to.shared.u64 t, %1; cvt.u32.u64 %0, t; }" : "=r"(a) : "l"(p));
    return a;
}
__device__ __forceinline__ void cp16(uint32_t dst, const void* src) {
    asm volatile("cp.async.cg.shared.global [%0], [%1], 16;" :: "r"(dst), "l"(src));
}
__device__ __forceinline__ void cp_commit() { asm volatile("cp.async.commit_group;" ::: "memory"); }
__device__ __forceinline__ void cp_wait0() { asm volatile("cp.async.wait_group 0;" ::: "memory"); }

__device__ __forceinline__ void ldsm4(uint32_t& r0, uint32_t& r1, uint32_t& r2, uint32_t& r3,
                                      uint32_t addr) {
    asm volatile("ldmatrix.sync.aligned.m8n8.x4.shared.b16 {%0,%1,%2,%3},[%4];"
                 : "=r"(r0), "=r"(r1), "=r"(r2), "=r"(r3) : "r"(addr));
}
__device__ __forceinline__ void mma_f16(float* c, const uint32_t* A, const uint32_t* B) {
    asm volatile(
        "mma.sync.aligned.m16n8k16.row.col.f32.f16.f16.f32 "
        "{%0,%1,%2,%3},{%4,%5,%6,%7},{%8,%9},{%0,%1,%2,%3};"
        : "+f"(c[0]), "+f"(c[1]), "+f"(c[2]), "+f"(c[3])
        : "r"(A[0]), "r"(A[1]), "r"(A[2]), "r"(A[3]), "r"(B[0]), "r"(B[1]));
}
__device__ __forceinline__ void split_f16(float f, __half& hi, __half& lo) {
    hi = __float2half(f);
    lo = __float2half(f - __half2float(hi));
}

// ------------- batched fp32 -> (hi,lo) fp16 converter (z-indexed) ----------
struct CvtHP {
    const float* src[4];
    __half *hi[4], *lo[4];
    long long strideE[4];
    int n4, seg4;
};

__global__ void cvt_batch_h(CvtHP p) {
    const int z = blockIdx.y;
    const float4* src = reinterpret_cast<const float4*>(p.src[z]);
    __half* hi = p.hi[z];
    __half* lo = p.lo[z];
    const long long strE = p.strideE[z];
    const int stride = gridDim.x * blockDim.x;
    for (int i = blockIdx.x * blockDim.x + threadIdx.x; i < p.n4; i += stride) {
        float4 v = src[i];
        int l = i / p.seg4, r = i - l * p.seg4;
        long long d = (long long)l * strE + (long long)r * 4;
        __half h0, h1, h2, h3, l0, l1, l2, l3;
        split_f16(v.x, h0, l0); split_f16(v.y, h1, l1);
        split_f16(v.z, h2, l2); split_f16(v.w, h3, l3);
        *reinterpret_cast<__half2*>(hi + d)     = __half2(h0, h1);
        *reinterpret_cast<__half2*>(hi + d + 2) = __half2(h2, h3);
        *reinterpret_cast<__half2*>(lo + d)     = __half2(l0, l1);
        *reinterpret_cast<__half2*>(lo + d + 2) = __half2(l2, l3);
    }
}

// ------ fp16 GEMM: C[M,N] = A * B^T, NP passes over B (hi[,lo]) ------------
// A single fp16. Kst = row stride; per-z base offsets (strA/strB) allow both
// batching and split-K. EPI: 0 = fp32 store, 3 = fp16 store (to Ch).
struct GemmHP {
    const __half *A, *Bh, *Bl;
    float* C;
    __half* Ch;
    long long strA, strB;
    int czDiv; long long czOut, czIn;
    int K, Kst, ldC;
};

template <int BM_, int BN_, int WR, int WC, int EPI, int NP>
__global__ void __launch_bounds__(WR * WC * 32, (WR * WC * 32) <= 128 ? 3 : 2)
gemm_h(GemmHP a) {
    constexpr int NT = WR * WC * 32;
    constexpr int ST_A = 0, ST_BH = BM_ * SP, ST_BL = (BM_ + BN_) * SP;
    constexpr int SE = (BM_ + NP * BN_) * SP;
    extern __shared__ __half smh[];

    const int tid = threadIdx.x;
    const int w = tid >> 5, lane = tid & 31;
    const int wm = w / WC, wn = w % WC;
    const int K = a.K, Kst = a.Kst;
    const int bm = blockIdx.y * BM_, bn = blockIdx.x * BN_;
    const int z = blockIdx.z;

    const long long cOff = (long long)(z / a.czDiv) * a.czOut +
                           (long long)(z % a.czDiv) * a.czIn;
    const __half* Ag = a.A + (long long)z * a.strA + (long long)bm * Kst;
    const __half* Bhg = a.Bh + (long long)z * a.strB + (long long)bn * Kst;
    const __half* Blg = (NP == 2) ? a.Bl + (long long)z * a.strB + (long long)bn * Kst : nullptr;

    float acc[4][4][4];
#pragma unroll
    for (int i = 0; i < 4; i++)
#pragma unroll
        for (int j = 0; j < 4; j++)
#pragma unroll
            for (int q = 0; q < 4; q++) acc[i][j][q] = 0.f;

    auto load_chunk = [&](int st, int kt) {
        __half* s = smh + st * SE;
        const int kof = kt * KC;
#pragma unroll 2
        for (int idx = tid; idx < BM_ * 4; idx += NT) {
            int row = idx >> 2, sg = idx & 3;
            cp16(smem_u32(s + ST_A + row * SP + sg * 8),
                 Ag + (long long)row * Kst + kof + sg * 8);
        }
#pragma unroll 2
        for (int idx = tid; idx < BN_ * 4; idx += NT) {
            int row = idx >> 2, sg = idx & 3;
            long long go = (long long)row * Kst + kof + sg * 8;
            cp16(smem_u32(s + ST_BH + row * SP + sg * 8), Bhg + go);
            if (NP == 2) cp16(smem_u32(s + ST_BL + row * SP + sg * 8), Blg + go);
        }
        cp_commit();
    };

    const int a_row = wm * 64 + (lane & 15);
    const int a_kof = (lane >> 4) * 8;
    const int b_row = wn * 32 + (lane >> 4) * 8 + (lane & 7);
    const int b_kof = ((lane >> 3) & 1) * 8;

    const int nch = K / KC;
    load_chunk(0, 0);

    for (int kt = 0; kt < nch; kt++) {
        cp_wait0();
        __syncthreads();
        if (kt + 1 < nch) load_chunk((kt + 1) & 1, kt + 1);

        const __half* s = smh + (kt & 1) * SE;
#pragma unroll
        for (int k16 = 0; k16 < KC / 16; k16++) {
            const int kk = k16 * 16;
            uint32_t af[4][4], bh_[4][2], bl_[4][2];
#pragma unroll
            for (int nt = 0; nt < 2; nt++) {
                ldsm4(bh_[2 * nt][0], bh_[2 * nt][1], bh_[2 * nt + 1][0], bh_[2 * nt + 1][1],
                      smem_u32(s + ST_BH + (b_row + nt * 16) * SP + b_kof + kk));
                if (NP == 2)
                    ldsm4(bl_[2 * nt][0], bl_[2 * nt][1], bl_[2 * nt + 1][0], bl_[2 * nt + 1][1],
                          smem_u32(s + ST_BL + (b_row + nt * 16) * SP + b_kof + kk));
            }
#pragma unroll
            for (int mi = 0; mi < 4; mi++)
                ldsm4(af[mi][0], af[mi][1], af[mi][2], af[mi][3],
                      smem_u32(s + ST_A + (a_row + mi * 16) * SP + a_kof + kk));
#pragma unroll
            for (int mi = 0; mi < 4; mi++)
#pragma unroll
                for (int ni = 0; ni < 4; ni++) mma_f16(acc[mi][ni], af[mi], bh_[ni]);
            if (NP == 2) {
#pragma unroll
                for (int mi = 0; mi < 4; mi++)
#pragma unroll
                    for (int ni = 0; ni < 4; ni++) mma_f16(acc[mi][ni], af[mi], bl_[ni]);
            }
        }
    }

    const int ldC = a.ldC;
#pragma unroll
    for (int mi = 0; mi < 4; mi++) {
#pragma unroll
        for (int ni = 0; ni < 4; ni++) {
            int row0 = bm + wm * 64 + mi * 16 + (lane >> 2);
            int col = bn + wn * 32 + ni * 8 + (lane & 3) * 2;
            long long o0 = cOff + (long long)row0 * ldC + col;
            long long o1 = cOff + (long long)(row0 + 8) * ldC + col;
            if (EPI == 3) {
                *reinterpret_cast<__half2*>(a.Ch + o0) =
                    __half2(__float2half(acc[mi][ni][0]), __float2half(acc[mi][ni][1]));
                *reinterpret_cast<__half2*>(a.Ch + o1) =
                    __half2(__float2half(acc[mi][ni][2]), __float2half(acc[mi][ni][3]));
            } else {
                *reinterpret_cast<float2*>(a.C + o0) =
                    make_float2(acc[mi][ni][0], acc[mi][ni][1]);
                *reinterpret_cast<float2*>(a.C + o1) =
                    make_float2(acc[mi][ni][2], acc[mi][ni][3]);
            }
        }
    }
}

// ------------------------------- elementwise -------------------------------
__global__ void embed_kernel(const int* __restrict__ tok, const float* __restrict__ emb) {
    int row = blockIdx.x;
    const float4* src = reinterpret_cast<const float4*>(emb + (size_t)tok[row] * kD);
    float4* dst = reinterpret_cast<float4*>(g_x + (size_t)row * kD);
    for (int i = threadIdx.x; i < kD / 4; i += blockDim.x) dst[i] = src[i];
}

__global__ void rmsnorm_cvt16(const float* __restrict__ in, const float* __restrict__ w,
                              __half* __restrict__ oh) {
    int row = blockIdx.x, tid = threadIdx.x;
    float4 v = reinterpret_cast<const float4*>(in + (size_t)row * kD)[tid];
    __shared__ float red[256];
    red[tid] = v.x * v.x + v.y * v.y + v.z * v.z + v.w * v.w;
    __syncthreads();
    for (int off = 128; off > 0; off >>= 1) {
        if (tid < off) red[tid] += red[tid + off];
        __syncthreads();
    }
    float inv = rsqrtf(red[0] * (1.f / kD) + kEPS);
    float4 wv = reinterpret_cast<const float4*>(w)[tid];
    size_t o = (size_t)row * kD + tid * 4;
    reinterpret_cast<__half2*>(oh + o)[0] =
        __half2(__float2half(v.x * inv * wv.x), __float2half(v.y * inv * wv.y));
    reinterpret_cast<__half2*>(oh + o)[1] =
        __half2(__float2half(v.z * inv * wv.z), __float2half(v.w * inv * wv.w));
}

// x += sum of 4 split-K partials; write x; then rmsnorm -> fp16
__global__ void rmsnorm_add_cvt16(float* __restrict__ x, const float* __restrict__ part,
                                  const float* __restrict__ w, __half* __restrict__ oh) {
    int row = blockIdx.x, tid = threadIdx.x;
    size_t o4 = (size_t)row * (kD / 4) + tid;
    float4 v = reinterpret_cast<float4*>(x)[o4];
#pragma unroll
    for (int s = 0; s < 4; s++) {
        float4 p = reinterpret_cast<const float4*>(part + (size_t)s * kBT * kD)[o4];
        v.x += p.x; v.y += p.y; v.z += p.z; v.w += p.w;
    }
    reinterpret_cast<float4*>(x)[o4] = v;
    __shared__ float red[256];
    red[tid] = v.x * v.x + v.y * v.y + v.z * v.z + v.w * v.w;
    __syncthreads();
    for (int off = 128; off > 0; off >>= 1) {
        if (tid < off) red[tid] += red[tid + off];
        __syncthreads();
    }
    float inv = rsqrtf(red[0] * (1.f / kD) + kEPS);
    float4 wv = reinterpret_cast<const float4*>(w)[tid];
    size_t o = (size_t)row * kD + tid * 4;
    reinterpret_cast<__half2*>(oh + o)[0] =
        __half2(__float2half(v.x * inv * wv.x), __float2half(v.y * inv * wv.y));
    reinterpret_cast<__half2*>(oh + o)[1] =
        __half2(__float2half(v.z * inv * wv.z), __float2half(v.w * inv * wv.w));
}

__global__ void rope_init() {
    int i = threadIdx.x;
    if (i < 32) g_inv[i] = (float)(1.0 / pow(10000.0, (double)(2 * i) / (double)kHD));
}

// RoPE on q,k -> single fp16 head-major; q pre-scaled by 1/sqrt(HD)
__global__ void rope_cvt(const int* __restrict__ pos) {
    int row = blockIdx.x, idx = threadIdx.x;
    int h = idx >> 5, i = idx & 31;
    int b = row >> 10, t = row & 1023;
    float ang = (float)pos[row] * g_inv[i];
    float s, c;
    sincosf(ang, &s, &c);
    const float* qs = g_qkv + (size_t)row * kD + h * kHD + 2 * i;
    const float* ks = qs + (size_t)kBT * kD;
    float qr = qs[0], qi = qs[1], kr = ks[0], ki = ks[1];
    size_t dst = ((size_t)(b * kH + h) * kT + t) * kHD + 2 * i;
    *reinterpret_cast<__half2*>(&h_q[dst]) =
        __half2(__float2half((qr * c - qi * s) * 0.125f),
                __float2half((qr * s + qi * c) * 0.125f));
    *reinterpret_cast<__half2*>(&h_k[dst]) =
        __half2(__float2half(kr * c - ki * s), __float2half(kr * s + ki * c));
}

__global__ void v_cvt() {
    __shared__ float vs[64][65];
    int bh = blockIdx.y, b = bh >> 4, h = bh & 15;
    int t0 = blockIdx.x * 64;
    const float* src = g_qkv + 2LL * kBT * kD + ((size_t)(b * kT + t0)) * kD + h * kHD;
#pragma unroll
    for (int it = 0; it < 16; it++) {
        int e = it * 256 + threadIdx.x;
        int tr = e >> 6, hd = e & 63;
        vs[tr][hd] = src[(size_t)tr * kD + hd];
    }
    __syncthreads();
#pragma unroll
    for (int it = 0; it < 16; it++) {
        int e = it * 256 + threadIdx.x;
        int hd = e >> 6, tc = e & 63;
        h_vt[((size_t)bh * kHD + hd) * kT + t0 + tc] = __float2half(vs[tc][hd]);
    }
}

// in-place softmax over fp16 rows of h_p
__global__ void softmax16() {
    size_t row = blockIdx.x;
    __half* p = h_p + row * (size_t)kT;
    __shared__ float red[256];
    int tid = threadIdx.x;
    float v[4], m = -1e30f;
#pragma unroll
    for (int j = 0; j < 4; j++) { v[j] = __half2float(p[tid + j * 256]); m = fmaxf(m, v[j]); }
    red[tid] = m;
    __syncthreads();
    for (int off = 128; off > 0; off >>= 1) {
        if (tid < off) red[tid] = fmaxf(red[tid], red[tid + off]);
        __syncthreads();
    }
    float M = red[0];
    __syncthreads();
    float sum = 0.f;
#pragma unroll
    for (int j = 0; j < 4; j++) { v[j] = expf(v[j] - M); sum += v[j]; }
    red[tid] = sum;
    __syncthreads();
    for (int off = 128; off > 0; off >>= 1) {
        if (tid < off) red[tid] += red[tid + off];
        __syncthreads();
    }
    float inv = 1.f / red[0];
#pragma unroll
    for (int j = 0; j < 4; j++)
        p[tid + j * 256] = __float2half(v[j] * inv);
}

__global__ void silu_cvt16() {
    int i4 = blockIdx.x * 256 + threadIdx.x;
    float4 a = reinterpret_cast<const float4*>(g_f13)[i4];
    float4 b = reinterpret_cast<const float4*>(g_f13)[i4 + kBT * kDFF / 4];
    size_t o = (size_t)i4 * 4;
    reinterpret_cast<__half2*>(h_g + o)[0] =
        __half2(__float2half(a.x / (1.f + expf(-a.x)) * b.x),
                __float2half(a.y / (1.f + expf(-a.y)) * b.y));
    reinterpret_cast<__half2*>(h_g + o)[1] =
        __half2(__float2half(a.z / (1.f + expf(-a.z)) * b.z),
                __float2half(a.w / (1.f + expf(-a.w)) * b.w));
}

// --------------------------------- launch ----------------------------------
namespace {
constexpr int SM_H2 = (128 + 2 * 64) * SP * 2 * NST;   // 40960 B (2-pass, BN=64)
constexpr int SM_S1 = (128 + 128) * SP * 2 * NST;      // 40960 B (1-pass, BN=128)
constexpr int SM_A1 = (128 + 64) * SP * 2 * NST;       // 30720 B (1-pass, BN=64)
}

extern "C" void kernel_launch(void* const* d_in, const int* in_sizes, int n_in,
                              void* d_out, int out_size) {
    const int* tok = (const int*)d_in[0];
    const int* pos = (const int*)d_in[1];
    const float* emb = (const float*)d_in[2];
    const float* attn_nw = (const float*)d_in[3];
    const float* wq = (const float*)d_in[4];
    const float* wk = (const float*)d_in[5];
    const float* wv = (const float*)d_in[6];
    const float* wo = (const float*)d_in[7];
    const float* ff_nw = (const float*)d_in[8];
    const float* w1 = (const float*)d_in[9];
    const float* w2 = (const float*)d_in[10];
    const float* w3 = (const float*)d_in[11];
    const float* norm_w = (const float*)d_in[12];
    float* out = (float*)d_out;

    cudaFuncSetAttribute(gemm_h<128, 64, 2, 2, 0, 2>, cudaFuncAttributeMaxDynamicSharedMemorySize, SM_H2);
    cudaFuncSetAttribute(gemm_h<128, 128, 2, 4, 3, 1>, cudaFuncAttributeMaxDynamicSharedMemorySize, SM_S1);
    cudaFuncSetAttribute(gemm_h<128, 64, 2, 2, 3, 1>, cudaFuncAttributeMaxDynamicSharedMemorySize, SM_A1);

    float *x, *qkv, *f13, *part;
    cudaGetSymbolAddress((void**)&x, g_x);
    cudaGetSymbolAddress((void**)&qkv, g_qkv);
    cudaGetSymbolAddress((void**)&f13, g_f13);
    cudaGetSymbolAddress((void**)&part, g_part);

    __half *ph, *po, *pg, *pq, *pk, *pvt, *pp;
    cudaGetSymbolAddress((void**)&ph, h_h);
    cudaGetSymbolAddress((void**)&po, h_o);
    cudaGetSymbolAddress((void**)&pg, h_g);
    cudaGetSymbolAddress((void**)&pq, h_q);
    cudaGetSymbolAddress((void**)&pk, h_k);
    cudaGetSymbolAddress((void**)&pvt, h_vt);
    cudaGetSymbolAddress((void**)&pp, h_p);
    __half *pwqkv[2], *pwo[2], *pw13[2], *pw2[2], *pemb[2];
    for (int si = 0; si < 2; si++) {
        cudaGetSymbolAddress((void**)&pwqkv[si], h_wqkv);
        cudaGetSymbolAddress((void**)&pwo[si], h_wo);
        cudaGetSymbolAddress((void**)&pw13[si], h_w13);
        cudaGetSymbolAddress((void**)&pw2[si], h_w2);
        cudaGetSymbolAddress((void**)&pemb[si], h_emb);
        pwqkv[si] += (size_t)si * kL * 3 * kD * kD;
        pwo[si] += (size_t)si * kL * kD * kD;
        pw13[si] += (size_t)si * kL * 2 * kDFF * kD;
        pw2[si] += (size_t)si * kL * kD * kDFF;
        pemb[si] += (size_t)si * kVOCAB * kD;
    }

    const int DD = kD * kD, FD = kDFF * kD;
    const long long PB = (long long)kBT * kD;

    // 0: wq,wk,wv interleave into h_wqkv; wo contiguous
    {
        CvtHP p{};
        p.src[0] = wq; p.src[1] = wk; p.src[2] = wv; p.src[3] = wo;
        p.hi[0] = pwqkv[0]; p.hi[1] = pwqkv[0] + DD; p.hi[2] = pwqkv[0] + 2 * DD; p.hi[3] = pwo[0];
        p.lo[0] = pwqkv[1]; p.lo[1] = pwqkv[1] + DD; p.lo[2] = pwqkv[1] + 2 * DD; p.lo[3] = pwo[1];
        p.strideE[0] = p.strideE[1] = p.strideE[2] = 3LL * DD;
        p.strideE[3] = DD;
        p.n4 = kL * DD / 4; p.seg4 = DD / 4;
        cvt_batch_h<<<dim3(1024, 4), 256>>>(p);
    }
    embed_kernel<<<kBT, 256>>>(tok, emb);                   // 1
    rmsnorm_cvt16<<<kBT, 256>>>(x, attn_nw, ph);            // 2

    GemmHP g{};
    g = GemmHP{ph, pwqkv[0], pwqkv[1], qkv, nullptr,
               0, DD, 1 << 20, 0, PB, kD, kD, kD};
    gemm_h<128, 64, 2, 2, 0, 2><<<dim3(16, 16, 3), 128, SM_H2>>>(g);  // 3: ncu target

    {   // 4: w1,w3 interleave; w2, emb contiguous
        CvtHP p{};
        p.src[0] = w1; p.src[1] = w3; p.src[2] = w2; p.src[3] = emb;
        p.hi[0] = pw13[0]; p.hi[1] = pw13[0] + FD; p.hi[2] = pw2[0]; p.hi[3] = pemb[0];
        p.lo[0] = pw13[1]; p.lo[1] = pw13[1] + FD; p.lo[2] = pw2[1]; p.lo[3] = pemb[1];
        p.strideE[0] = p.strideE[1] = 2LL * FD;
        p.strideE[2] = FD; p.strideE[3] = FD;
        p.n4 = kL * FD / 4; p.seg4 = FD / 4;
        cvt_batch_h<<<dim3(2048, 4), 256>>>(p);
    }
    rope_init<<<1, 32>>>();                                 // 5

    for (int l = 0; l < kL; l++) {
        if (l > 0) {
            rmsnorm_add_cvt16<<<kBT, 256>>>(x, part, attn_nw + (size_t)l * kD, ph);
            g = GemmHP{ph, pwqkv[0] + (size_t)l * 3 * DD, pwqkv[1] + (size_t)l * 3 * DD,
                       qkv, nullptr, 0, DD, 1 << 20, 0, PB, kD, kD, kD};
            gemm_h<128, 64, 2, 2, 0, 2><<<dim3(16, 16, 3), 128, SM_H2>>>(g);
        }
        rope_cvt<<<kBT, 512>>>(pos);
        v_cvt<<<dim3(kT / 64, kBH), 256>>>();
        // scores: q*k^T (fp16, scale folded into q) -> fp16 h_p
        g = GemmHP{pq, pk, nullptr, nullptr, pp,
                   (long long)kT * kHD, (long long)kT * kHD,
                   1 << 20, 0, (long long)kT * kT, kHD, kHD, kT};
        gemm_h<128, 128, 2, 4, 3, 1><<<dim3(8, 8, kBH), 256, SM_S1>>>(g);
        softmax16<<<kBH * kT, 256>>>();
        // av: P*V^T -> fp16 h_o
        g = GemmHP{pp, pvt, nullptr, nullptr, po,
                   (long long)kT * kT, (long long)kHD * kT,
                   kH, (long long)kT * kD, kHD, kT, kT, kD};
        gemm_h<128, 64, 2, 2, 3, 1><<<dim3(1, 8, kBH), 128, SM_A1>>>(g);
        // wo: split-K x4 into partials (K=256 each)
        g = GemmHP{po, pwo[0] + (size_t)l * DD, pwo[1] + (size_t)l * DD,
                   part, nullptr, 256, 256, 1, PB, 0, 256, kD, kD};
        gemm_h<128, 64, 2, 2, 0, 2><<<dim3(16, 16, 4), 128, SM_H2>>>(g);
        // --- FFN ---
        rmsnorm_add_cvt16<<<kBT, 256>>>(x, part, ff_nw + (size_t)l * kD, ph);
        g = GemmHP{ph, pw13[0] + (size_t)l * 2 * FD, pw13[1] + (size_t)l * 2 * FD,
                   f13, nullptr, 0, FD, 1 << 20, 0, (long long)kBT * kDFF, kD, kD, kDFF};
        gemm_h<128, 64, 2, 2, 0, 2><<<dim3(64, 16, 2), 128, SM_H2>>>(g);
        silu_cvt16<<<kBT * kDFF / 1024, 256>>>();
        // w2: split-K x4 into partials (K=1024 each, Kst=4096)
        g = GemmHP{pg, pw2[0] + (size_t)l * kD * kDFF, pw2[1] + (size_t)l * kD * kDFF,
                   part, nullptr, 1024, 1024, 1, PB, 0, 1024, kDFF, kD};
        gemm_h<128, 64, 2, 2, 0, 2><<<dim3(16, 16, 4), 128, SM_H2>>>(g);
    }

    // --- final: x += w2 partials, norm, tied LM head ---
    rmsnorm_add_cvt16<<<kBT, 256>>>(x, part, norm_w, ph);
    GemmHP g2{ph, pemb[0], pemb[1], out, nullptr,
              0, 0, 1 << 20, 0, 0, kD, kD, kVOCAB};
    gemm_h<128, 64, 2, 2, 0, 2><<<dim3(kVOCAB / 64, 16, 1), 128, SM_H2>>>(g2);
}

// round 17
// speedup vs baseline: 1.6842x; 1.1477x over previous
#include <cuda_runtime.h>
#include <cuda_fp16.h>
#include <cstdint>
#include <math.h>

namespace {
constexpr int kB = 2, kT = 1024, kD = 1024, kH = 16, kHD = 64, kL = 4;
constexpr int kDFF = 4096, kVOCAB = 16384;
constexpr int kBT = kB * kT;
constexpr int kBH = kB * kH;
constexpr float kEPS = 1e-6f;
constexpr int KC = 32;     // k-chunk
constexpr int SP = 40;     // padded smem row stride (16-bit elems)
constexpr int NST = 2;     // pipeline stages
}

// ------------------------- static device scratch ---------------------------
__device__ float g_x[kBT * kD];
__device__ float g_qkv[3 * kBT * kD];
__device__ float g_f13[2 * kBT * kDFF];
__device__ float g_part[4 * kBT * kD];    // split-K partial sums
__device__ float g_inv[32];

__device__ __half h_h[kBT * kD];
__device__ __half h_o[kBT * kD];
__device__ __half h_g[kBT * kDFF];
__device__ __half h_q[kBH * kT * kHD];
__device__ __half h_k[kBH * kT * kHD];
__device__ __half h_vt[kBH * kHD * kT];
__device__ __half h_p[(size_t)kBH * kT * kT];  // scores -> probs (in place)
__device__ __half h_wqkv[2][kL * 3 * kD * kD];
__device__ __half h_wo[2][kL * kD * kD];
__device__ __half h_w13[2][kL * 2 * kDFF * kD];
__device__ __half h_w2[2][kL * kD * kDFF];
__device__ __half h_emb[2][kVOCAB * kD];

// ------------------------------ PTX helpers --------------------------------
__device__ __forceinline__ uint32_t smem_u32(const void* p) {
    uint32_t a;
    asm("{ .reg .u64 t; cvta.to.shared.u64 t, %1; cvt.u32.u64 %0, t; }" : "=r"(a) : "l"(p));
    return a;
}
__device__ __forceinline__ void cp16(uint32_t dst, const void* src) {
    asm volatile("cp.async.cg.shared.global [%0], [%1], 16;" :: "r"(dst), "l"(src));
}
__device__ __forceinline__ void cp_commit() { asm volatile("cp.async.commit_group;" ::: "memory"); }
__device__ __forceinline__ void cp_wait0() { asm volatile("cp.async.wait_group 0;" ::: "memory"); }

__device__ __forceinline__ void ldsm4(uint32_t& r0, uint32_t& r1, uint32_t& r2, uint32_t& r3,
                                      uint32_t addr) {
    asm volatile("ldmatrix.sync.aligned.m8n8.x4.shared.b16 {%0,%1,%2,%3},[%4];"
                 : "=r"(r0), "=r"(r1), "=r"(r2), "=r"(r3) : "r"(addr));
}
__device__ __forceinline__ void mma_f16(float* c, const uint32_t* A, const uint32_t* B) {
    asm volatile(
        "mma.sync.aligned.m16n8k16.row.col.f32.f16.f16.f32 "
        "{%0,%1,%2,%3},{%4,%5,%6,%7},{%8,%9},{%0,%1,%2,%3};"
        : "+f"(c[0]), "+f"(c[1]), "+f"(c[2]), "+f"(c[3])
        : "r"(A[0]), "r"(A[1]), "r"(A[2]), "r"(A[3]), "r"(B[0]), "r"(B[1]));
}
__device__ __forceinline__ void split_f16(float f, __half& hi, __half& lo) {
    hi = __float2half(f);
    lo = __float2half(f - __half2float(hi));
}

// ------------- batched fp32 -> (hi,lo) fp16 converter (z-indexed) ----------
struct CvtHP {
    const float* src[4];
    __half *hi[4], *lo[4];
    long long strideE[4];
    int n4, seg4;
};

__global__ void cvt_batch_h(CvtHP p) {
    const int z = blockIdx.y;
    const float4* src = reinterpret_cast<const float4*>(p.src[z]);
    __half* hi = p.hi[z];
    __half* lo = p.lo[z];
    const long long strE = p.strideE[z];
    const int stride = gridDim.x * blockDim.x;
    for (int i = blockIdx.x * blockDim.x + threadIdx.x; i < p.n4; i += stride) {
        float4 v = src[i];
        int l = i / p.seg4, r = i - l * p.seg4;
        long long d = (long long)l * strE + (long long)r * 4;
        __half h0, h1, h2, h3, l0, l1, l2, l3;
        split_f16(v.x, h0, l0); split_f16(v.y, h1, l1);
        split_f16(v.z, h2, l2); split_f16(v.w, h3, l3);
        *reinterpret_cast<__half2*>(hi + d)     = __half2(h0, h1);
        *reinterpret_cast<__half2*>(hi + d + 2) = __half2(h2, h3);
        *reinterpret_cast<__half2*>(lo + d)     = __half2(l0, l1);
        *reinterpret_cast<__half2*>(lo + d + 2) = __half2(l2, l3);
    }
}

// ------ fp16 GEMM: C[M,N] = A * B^T, NP passes over B (hi[,lo]) ------------
// A single fp16. Kst = row stride; per-z base offsets (strA/strB) allow both
// batching and split-K. EPI: 0 = fp32 store, 3 = fp16 store (to Ch).
struct GemmHP {
    const __half *A, *Bh, *Bl;
    float* C;
    __half* Ch;
    long long strA, strB;
    int czDiv; long long czOut, czIn;
    int K, Kst, ldC;
};

template <int BM_, int BN_, int WR, int WC, int EPI, int NP>
__global__ void __launch_bounds__(WR * WC * 32, (WR * WC * 32) <= 128 ? 3 : 2)
gemm_h(GemmHP a) {
    constexpr int NT = WR * WC * 32;
    constexpr int ST_A = 0, ST_BH = BM_ * SP, ST_BL = (BM_ + BN_) * SP;
    constexpr int SE = (BM_ + NP * BN_) * SP;
    extern __shared__ __half smh[];

    const int tid = threadIdx.x;
    const int w = tid >> 5, lane = tid & 31;
    const int wm = w / WC, wn = w % WC;
    const int K = a.K, Kst = a.Kst;
    const int bm = blockIdx.y * BM_, bn = blockIdx.x * BN_;
    const int z = blockIdx.z;

    const long long cOff = (long long)(z / a.czDiv) * a.czOut +
                           (long long)(z % a.czDiv) * a.czIn;
    const __half* Ag = a.A + (long long)z * a.strA + (long long)bm * Kst;
    const __half* Bhg = a.Bh + (long long)z * a.strB + (long long)bn * Kst;
    const __half* Blg = (NP == 2) ? a.Bl + (long long)z * a.strB + (long long)bn * Kst : nullptr;

    float acc[4][4][4];
#pragma unroll
    for (int i = 0; i < 4; i++)
#pragma unroll
        for (int j = 0; j < 4; j++)
#pragma unroll
            for (int q = 0; q < 4; q++) acc[i][j][q] = 0.f;

    auto load_chunk = [&](int st, int kt) {
        __half* s = smh + st * SE;
        const int kof = kt * KC;
#pragma unroll 2
        for (int idx = tid; idx < BM_ * 4; idx += NT) {
            int row = idx >> 2, sg = idx & 3;
            cp16(smem_u32(s + ST_A + row * SP + sg * 8),
                 Ag + (long long)row * Kst + kof + sg * 8);
        }
#pragma unroll 2
        for (int idx = tid; idx < BN_ * 4; idx += NT) {
            int row = idx >> 2, sg = idx & 3;
            long long go = (long long)row * Kst + kof + sg * 8;
            cp16(smem_u32(s + ST_BH + row * SP + sg * 8), Bhg + go);
            if (NP == 2) cp16(smem_u32(s + ST_BL + row * SP + sg * 8), Blg + go);
        }
        cp_commit();
    };

    const int a_row = wm * 64 + (lane & 15);
    const int a_kof = (lane >> 4) * 8;
    const int b_row = wn * 32 + (lane >> 4) * 8 + (lane & 7);
    const int b_kof = ((lane >> 3) & 1) * 8;

    const int nch = K / KC;
    load_chunk(0, 0);

    for (int kt = 0; kt < nch; kt++) {
        cp_wait0();
        __syncthreads();
        if (kt + 1 < nch) load_chunk((kt + 1) & 1, kt + 1);

        const __half* s = smh + (kt & 1) * SE;
#pragma unroll
        for (int k16 = 0; k16 < KC / 16; k16++) {
            const int kk = k16 * 16;
            uint32_t af[4][4], bh_[4][2], bl_[4][2];
#pragma unroll
            for (int nt = 0; nt < 2; nt++) {
                ldsm4(bh_[2 * nt][0], bh_[2 * nt][1], bh_[2 * nt + 1][0], bh_[2 * nt + 1][1],
                      smem_u32(s + ST_BH + (b_row + nt * 16) * SP + b_kof + kk));
                if (NP == 2)
                    ldsm4(bl_[2 * nt][0], bl_[2 * nt][1], bl_[2 * nt + 1][0], bl_[2 * nt + 1][1],
                          smem_u32(s + ST_BL + (b_row + nt * 16) * SP + b_kof + kk));
            }
#pragma unroll
            for (int mi = 0; mi < 4; mi++)
                ldsm4(af[mi][0], af[mi][1], af[mi][2], af[mi][3],
                      smem_u32(s + ST_A + (a_row + mi * 16) * SP + a_kof + kk));
#pragma unroll
            for (int mi = 0; mi < 4; mi++)
#pragma unroll
                for (int ni = 0; ni < 4; ni++) mma_f16(acc[mi][ni], af[mi], bh_[ni]);
            if (NP == 2) {
#pragma unroll
                for (int mi = 0; mi < 4; mi++)
#pragma unroll
                    for (int ni = 0; ni < 4; ni++) mma_f16(acc[mi][ni], af[mi], bl_[ni]);
            }
        }
    }

    const int ldC = a.ldC;
#pragma unroll
    for (int mi = 0; mi < 4; mi++) {
#pragma unroll
        for (int ni = 0; ni < 4; ni++) {
            int row0 = bm + wm * 64 + mi * 16 + (lane >> 2);
            int col = bn + wn * 32 + ni * 8 + (lane & 3) * 2;
            long long o0 = cOff + (long long)row0 * ldC + col;
            long long o1 = cOff + (long long)(row0 + 8) * ldC + col;
            if (EPI == 3) {
                *reinterpret_cast<__half2*>(a.Ch + o0) =
                    __half2(__float2half(acc[mi][ni][0]), __float2half(acc[mi][ni][1]));
                *reinterpret_cast<__half2*>(a.Ch + o1) =
                    __half2(__float2half(acc[mi][ni][2]), __float2half(acc[mi][ni][3]));
            } else {
                *reinterpret_cast<float2*>(a.C + o0) =
                    make_float2(acc[mi][ni][0], acc[mi][ni][1]);
                *reinterpret_cast<float2*>(a.C + o1) =
                    make_float2(acc[mi][ni][2], acc[mi][ni][3]);
            }
        }
    }
}

// ------------------------------- elementwise -------------------------------
__global__ void embed_kernel(const int* __restrict__ tok, const float* __restrict__ emb) {
    int row = blockIdx.x;
    const float4* src = reinterpret_cast<const float4*>(emb + (size_t)tok[row] * kD);
    float4* dst = reinterpret_cast<float4*>(g_x + (size_t)row * kD);
    for (int i = threadIdx.x; i < kD / 4; i += blockDim.x) dst[i] = src[i];
}

__global__ void rmsnorm_cvt16(const float* __restrict__ in, const float* __restrict__ w,
                              __half* __restrict__ oh) {
    int row = blockIdx.x, tid = threadIdx.x;
    float4 v = reinterpret_cast<const float4*>(in + (size_t)row * kD)[tid];
    __shared__ float red[256];
    red[tid] = v.x * v.x + v.y * v.y + v.z * v.z + v.w * v.w;
    __syncthreads();
    for (int off = 128; off > 0; off >>= 1) {
        if (tid < off) red[tid] += red[tid + off];
        __syncthreads();
    }
    float inv = rsqrtf(red[0] * (1.f / kD) + kEPS);
    float4 wv = reinterpret_cast<const float4*>(w)[tid];
    size_t o = (size_t)row * kD + tid * 4;
    reinterpret_cast<__half2*>(oh + o)[0] =
        __half2(__float2half(v.x * inv * wv.x), __float2half(v.y * inv * wv.y));
    reinterpret_cast<__half2*>(oh + o)[1] =
        __half2(__float2half(v.z * inv * wv.z), __float2half(v.w * inv * wv.w));
}

// x += sum of 4 split-K partials; write x; then rmsnorm -> fp16
__global__ void rmsnorm_add_cvt16(float* __restrict__ x, const float* __restrict__ part,
                                  const float* __restrict__ w, __half* __restrict__ oh) {
    int row = blockIdx.x, tid = threadIdx.x;
    size_t o4 = (size_t)row * (kD / 4) + tid;
    float4 v = reinterpret_cast<float4*>(x)[o4];
#pragma unroll
    for (int s = 0; s < 4; s++) {
        float4 p = reinterpret_cast<const float4*>(part + (size_t)s * kBT * kD)[o4];
        v.x += p.x; v.y += p.y; v.z += p.z; v.w += p.w;
    }
    reinterpret_cast<float4*>(x)[o4] = v;
    __shared__ float red[256];
    red[tid] = v.x * v.x + v.y * v.y + v.z * v.z + v.w * v.w;
    __syncthreads();
    for (int off = 128; off > 0; off >>= 1) {
        if (tid < off) red[tid] += red[tid + off];
        __syncthreads();
    }
    float inv = rsqrtf(red[0] * (1.f / kD) + kEPS);
    float4 wv = reinterpret_cast<const float4*>(w)[tid];
    size_t o = (size_t)row * kD + tid * 4;
    reinterpret_cast<__half2*>(oh + o)[0] =
        __half2(__float2half(v.x * inv * wv.x), __float2half(v.y * inv * wv.y));
    reinterpret_cast<__half2*>(oh + o)[1] =
        __half2(__float2half(v.z * inv * wv.z), __float2half(v.w * inv * wv.w));
}

__global__ void rope_init() {
    int i = threadIdx.x;
    if (i < 32) g_inv[i] = (float)(1.0 / pow(10000.0, (double)(2 * i) / (double)kHD));
}

// RoPE on q,k -> single fp16 head-major; q pre-scaled by 1/sqrt(HD)
__global__ void rope_cvt(const int* __restrict__ pos) {
    int row = blockIdx.x, idx = threadIdx.x;
    int h = idx >> 5, i = idx & 31;
    int b = row >> 10, t = row & 1023;
    float ang = (float)pos[row] * g_inv[i];
    float s, c;
    sincosf(ang, &s, &c);
    const float* qs = g_qkv + (size_t)row * kD + h * kHD + 2 * i;
    const float* ks = qs + (size_t)kBT * kD;
    float qr = qs[0], qi = qs[1], kr = ks[0], ki = ks[1];
    size_t dst = ((size_t)(b * kH + h) * kT + t) * kHD + 2 * i;
    *reinterpret_cast<__half2*>(&h_q[dst]) =
        __half2(__float2half((qr * c - qi * s) * 0.125f),
                __float2half((qr * s + qi * c) * 0.125f));
    *reinterpret_cast<__half2*>(&h_k[dst]) =
        __half2(__float2half(kr * c - ki * s), __float2half(kr * s + ki * c));
}

__global__ void v_cvt() {
    __shared__ float vs[64][65];
    int bh = blockIdx.y, b = bh >> 4, h = bh & 15;
    int t0 = blockIdx.x * 64;
    const float* src = g_qkv + 2LL * kBT * kD + ((size_t)(b * kT + t0)) * kD + h * kHD;
#pragma unroll
    for (int it = 0; it < 16; it++) {
        int e = it * 256 + threadIdx.x;
        int tr = e >> 6, hd = e & 63;
        vs[tr][hd] = src[(size_t)tr * kD + hd];
    }
    __syncthreads();
#pragma unroll
    for (int it = 0; it < 16; it++) {
        int e = it * 256 + threadIdx.x;
        int hd = e >> 6, tc = e & 63;
        h_vt[((size_t)bh * kHD + hd) * kT + t0 + tc] = __float2half(vs[tc][hd]);
    }
}

// in-place softmax over fp16 rows of h_p
__global__ void softmax16() {
    size_t row = blockIdx.x;
    __half* p = h_p + row * (size_t)kT;
    __shared__ float red[256];
    int tid = threadIdx.x;
    float v[4], m = -1e30f;
#pragma unroll
    for (int j = 0; j < 4; j++) { v[j] = __half2float(p[tid + j * 256]); m = fmaxf(m, v[j]); }
    red[tid] = m;
    __syncthreads();
    for (int off = 128; off > 0; off >>= 1) {
        if (tid < off) red[tid] = fmaxf(red[tid], red[tid + off]);
        __syncthreads();
    }
    float M = red[0];
    __syncthreads();
    float sum = 0.f;
#pragma unroll
    for (int j = 0; j < 4; j++) { v[j] = expf(v[j] - M); sum += v[j]; }
    red[tid] = sum;
    __syncthreads();
    for (int off = 128; off > 0; off >>= 1) {
        if (tid < off) red[tid] += red[tid + off];
        __syncthreads();
    }
    float inv = 1.f / red[0];
#pragma unroll
    for (int j = 0; j < 4; j++)
        p[tid + j * 256] = __float2half(v[j] * inv);
}

__global__ void silu_cvt16() {
    int i4 = blockIdx.x * 256 + threadIdx.x;
    float4 a = reinterpret_cast<const float4*>(g_f13)[i4];
    float4 b = reinterpret_cast<const float4*>(g_f13)[i4 + kBT * kDFF / 4];
    size_t o = (size_t)i4 * 4;
    reinterpret_cast<__half2*>(h_g + o)[0] =
        __half2(__float2half(a.x / (1.f + expf(-a.x)) * b.x),
                __float2half(a.y / (1.f + expf(-a.y)) * b.y));
    reinterpret_cast<__half2*>(h_g + o)[1] =
        __half2(__float2half(a.z / (1.f + expf(-a.z)) * b.z),
                __float2half(a.w / (1.f + expf(-a.w)) * b.w));
}

// --------------------------------- launch ----------------------------------
namespace {
constexpr int SM_H2 = (128 + 2 * 64) * SP * 2 * NST;   // 40960 B (2-pass, BN=64)
constexpr int SM_S1 = (128 + 128) * SP * 2 * NST;      // 40960 B (1-pass, BN=128)
constexpr int SM_A1 = (128 + 64) * SP * 2 * NST;       // 30720 B (1-pass, BN=64)
}

extern "C" void kernel_launch(void* const* d_in, const int* in_sizes, int n_in,
                              void* d_out, int out_size) {
    const int* tok = (const int*)d_in[0];
    const int* pos = (const int*)d_in[1];
    const float* emb = (const float*)d_in[2];
    const float* attn_nw = (const float*)d_in[3];
    const float* wq = (const float*)d_in[4];
    const float* wk = (const float*)d_in[5];
    const float* wv = (const float*)d_in[6];
    const float* wo = (const float*)d_in[7];
    const float* ff_nw = (const float*)d_in[8];
    const float* w1 = (const float*)d_in[9];
    const float* w2 = (const float*)d_in[10];
    const float* w3 = (const float*)d_in[11];
    const float* norm_w = (const float*)d_in[12];
    float* out = (float*)d_out;

    cudaFuncSetAttribute(gemm_h<128, 64, 2, 2, 0, 2>, cudaFuncAttributeMaxDynamicSharedMemorySize, SM_H2);
    cudaFuncSetAttribute(gemm_h<128, 64, 2, 2, 0, 1>, cudaFuncAttributeMaxDynamicSharedMemorySize, SM_A1);
    cudaFuncSetAttribute(gemm_h<128, 128, 2, 4, 3, 1>, cudaFuncAttributeMaxDynamicSharedMemorySize, SM_S1);
    cudaFuncSetAttribute(gemm_h<128, 64, 2, 2, 3, 1>, cudaFuncAttributeMaxDynamicSharedMemorySize, SM_A1);

    float *x, *qkv, *f13, *part;
    cudaGetSymbolAddress((void**)&x, g_x);
    cudaGetSymbolAddress((void**)&qkv, g_qkv);
    cudaGetSymbolAddress((void**)&f13, g_f13);
    cudaGetSymbolAddress((void**)&part, g_part);

    __half *ph, *po, *pg, *pq, *pk, *pvt, *pp;
    cudaGetSymbolAddress((void**)&ph, h_h);
    cudaGetSymbolAddress((void**)&po, h_o);
    cudaGetSymbolAddress((void**)&pg, h_g);
    cudaGetSymbolAddress((void**)&pq, h_q);
    cudaGetSymbolAddress((void**)&pk, h_k);
    cudaGetSymbolAddress((void**)&pvt, h_vt);
    cudaGetSymbolAddress((void**)&pp, h_p);
    __half *pwqkv[2], *pwo[2], *pw13[2], *pw2[2], *pemb[2];
    for (int si = 0; si < 2; si++) {
        cudaGetSymbolAddress((void**)&pwqkv[si], h_wqkv);
        cudaGetSymbolAddress((void**)&pwo[si], h_wo);
        cudaGetSymbolAddress((void**)&pw13[si], h_w13);
        cudaGetSymbolAddress((void**)&pw2[si], h_w2);
        cudaGetSymbolAddress((void**)&pemb[si], h_emb);
        pwqkv[si] += (size_t)si * kL * 3 * kD * kD;
        pwo[si] += (size_t)si * kL * kD * kD;
        pw13[si] += (size_t)si * kL * 2 * kDFF * kD;
        pw2[si] += (size_t)si * kL * kD * kDFF;
        pemb[si] += (size_t)si * kVOCAB * kD;
    }

    const int DD = kD * kD, FD = kDFF * kD;
    const long long PB = (long long)kBT * kD;

    // 0: wq,wk,wv interleave into h_wqkv; wo contiguous
    {
        CvtHP p{};
        p.src[0] = wq; p.src[1] = wk; p.src[2] = wv; p.src[3] = wo;
        p.hi[0] = pwqkv[0]; p.hi[1] = pwqkv[0] + DD; p.hi[2] = pwqkv[0] + 2 * DD; p.hi[3] = pwo[0];
        p.lo[0] = pwqkv[1]; p.lo[1] = pwqkv[1] + DD; p.lo[2] = pwqkv[1] + 2 * DD; p.lo[3] = pwo[1];
        p.strideE[0] = p.strideE[1] = p.strideE[2] = 3LL * DD;
        p.strideE[3] = DD;
        p.n4 = kL * DD / 4; p.seg4 = DD / 4;
        cvt_batch_h<<<dim3(1024, 4), 256>>>(p);
    }
    embed_kernel<<<kBT, 256>>>(tok, emb);                   // 1
    rmsnorm_cvt16<<<kBT, 256>>>(x, attn_nw, ph);            // 2

    GemmHP g{};
    g = GemmHP{ph, pwqkv[0], pwqkv[1], qkv, nullptr,
               0, DD, 1 << 20, 0, PB, kD, kD, kD};
    gemm_h<128, 64, 2, 2, 0, 2><<<dim3(16, 16, 3), 128, SM_H2>>>(g);  // 3: ncu target

    {   // 4: w1,w3 interleave; w2, emb contiguous
        CvtHP p{};
        p.src[0] = w1; p.src[1] = w3; p.src[2] = w2; p.src[3] = emb;
        p.hi[0] = pw13[0]; p.hi[1] = pw13[0] + FD; p.hi[2] = pw2[0]; p.hi[3] = pemb[0];
        p.lo[0] = pw13[1]; p.lo[1] = pw13[1] + FD; p.lo[2] = pw2[1]; p.lo[3] = pemb[1];
        p.strideE[0] = p.strideE[1] = 2LL * FD;
        p.strideE[2] = FD; p.strideE[3] = FD;
        p.n4 = kL * FD / 4; p.seg4 = FD / 4;
        cvt_batch_h<<<dim3(2048, 4), 256>>>(p);
    }
    rope_init<<<1, 32>>>();                                 // 5

    for (int l = 0; l < kL; l++) {
        if (l > 0) {
            rmsnorm_add_cvt16<<<kBT, 256>>>(x, part, attn_nw + (size_t)l * kD, ph);
            g = GemmHP{ph, pwqkv[0] + (size_t)l * 3 * DD, pwqkv[1] + (size_t)l * 3 * DD,
                       qkv, nullptr, 0, DD, 1 << 20, 0, PB, kD, kD, kD};
            gemm_h<128, 64, 2, 2, 0, 2><<<dim3(16, 16, 3), 128, SM_H2>>>(g);
        }
        rope_cvt<<<kBT, 512>>>(pos);
        v_cvt<<<dim3(kT / 64, kBH), 256>>>();
        // scores: q*k^T (fp16, scale folded into q) -> fp16 h_p
        g = GemmHP{pq, pk, nullptr, nullptr, pp,
                   (long long)kT * kHD, (long long)kT * kHD,
                   1 << 20, 0, (long long)kT * kT, kHD, kHD, kT};
        gemm_h<128, 128, 2, 4, 3, 1><<<dim3(8, 8, kBH), 256, SM_S1>>>(g);
        softmax16<<<kBH * kT, 256>>>();
        // av: P*V^T -> fp16 h_o
        g = GemmHP{pp, pvt, nullptr, nullptr, po,
                   (long long)kT * kT, (long long)kHD * kT,
                   kH, (long long)kT * kD, kHD, kT, kT, kD};
        gemm_h<128, 64, 2, 2, 3, 1><<<dim3(1, 8, kBH), 128, SM_A1>>>(g);
        // wo: split-K x4 into partials (K=256 each, 2-pass)
        g = GemmHP{po, pwo[0] + (size_t)l * DD, pwo[1] + (size_t)l * DD,
                   part, nullptr, 256, 256, 1, PB, 0, 256, kD, kD};
        gemm_h<128, 64, 2, 2, 0, 2><<<dim3(16, 16, 4), 128, SM_H2>>>(g);
        // --- FFN ---
        rmsnorm_add_cvt16<<<kBT, 256>>>(x, part, ff_nw + (size_t)l * kD, ph);
        // w13: single-fp16 weights (1-pass)
        g = GemmHP{ph, pw13[0] + (size_t)l * 2 * FD, nullptr,
                   f13, nullptr, 0, FD, 1 << 20, 0, (long long)kBT * kDFF, kD, kD, kDFF};
        gemm_h<128, 64, 2, 2, 0, 1><<<dim3(64, 16, 2), 128, SM_A1>>>(g);
        silu_cvt16<<<kBT * kDFF / 1024, 256>>>();
        // w2: split-K x4 into partials (K=1024 each, Kst=4096, 2-pass)
        g = GemmHP{pg, pw2[0] + (size_t)l * kD * kDFF, pw2[1] + (size_t)l * kD * kDFF,
                   part, nullptr, 1024, 1024, 1, PB, 0, 1024, kDFF, kD};
        gemm_h<128, 64, 2, 2, 0, 2><<<dim3(16, 16, 4), 128, SM_H2>>>(g);
    }

    // --- final: x += w2 partials, norm, tied LM head (1-pass fp16 emb) ---
    rmsnorm_add_cvt16<<<kBT, 256>>>(x, part, norm_w, ph);
    GemmHP g2{ph, pemb[0], nullptr, out, nullptr,
              0, 0, 1 << 20, 0, 0, kD, kD, kVOCAB};
    gemm_h<128, 64, 2, 2, 0, 1><<<dim3(kVOCAB / 64, 16, 1), 128, SM_A1>>>(g2);
}